// round 2
// baseline (speedup 1.0000x reference)
#include <cuda_runtime.h>
#include <cuda_fp16.h>
#include <math.h>

// Problem constants (fixed shapes for this problem)
#define H   1024
#define FF  4096
#define E   8
#define T_MAX 8192

// GEMM tiling
#define BM 128
#define BN 64
#define BK 16

// ---------------- device scratch (no allocation allowed) ----------------
__device__ int   g_counts[E];
__device__ int   g_base[E];
__device__ int   g_list[E * T_MAX];          // packed token*2 + slot
__device__ float g_wts[T_MAX * 2];           // combine weight per (token, slot)
__device__ float g_act[(size_t)(2 * T_MAX) * FF];   // 256 MB: silu(x@w1^T)*(x@w3^T), grouped by expert
__device__ float g_ybuf[(size_t)T_MAX * 2 * H];     // 64 MB: per-slot expert outputs (pre-scaled)

// ---------------- kernels ----------------

__global__ void k_zero() {
    if (threadIdx.x < E) g_counts[threadIdx.x] = 0;
}

// One warp per token: fp32 logits, softmax, top-2, renorm, list build.
__global__ void k_router(const float* __restrict__ x,
                         const float* __restrict__ gate,
                         float* __restrict__ logits_out, int T) {
    __shared__ float sg[E * H];  // 32 KB
    for (int i = threadIdx.x; i < E * H; i += blockDim.x) sg[i] = gate[i];
    __syncthreads();

    int warp = threadIdx.x >> 5;
    int lane = threadIdx.x & 31;
    int t = blockIdx.x * 8 + warp;
    if (t >= T) return;

    const float* xr = x + (size_t)t * H;
    float acc[E];
#pragma unroll
    for (int e = 0; e < E; e++) acc[e] = 0.f;

    for (int k = lane; k < H; k += 32) {
        float xv = xr[k];
#pragma unroll
        for (int e = 0; e < E; e++) acc[e] += xv * sg[e * H + k];
    }
#pragma unroll
    for (int e = 0; e < E; e++) {
#pragma unroll
        for (int o = 16; o > 0; o >>= 1)
            acc[e] += __shfl_down_sync(0xffffffffu, acc[e], o);
    }

    if (lane == 0) {
#pragma unroll
        for (int e = 0; e < E; e++) logits_out[(size_t)t * E + e] = acc[e];

        // top-2 on logits (same ordering as on softmax probs); ties -> lower index
        int e0 = 0; float l0 = acc[0];
#pragma unroll
        for (int e = 1; e < E; e++) if (acc[e] > l0) { l0 = acc[e]; e0 = e; }
        int e1 = -1; float l1 = -1e30f;
#pragma unroll
        for (int e = 0; e < E; e++) if (e != e0 && acc[e] > l1) { l1 = acc[e]; e1 = e; }

        // softmax probs (fp32, max-subtracted), renormalized over the top-2
        float s = 0.f;
        float pe[E];
#pragma unroll
        for (int e = 0; e < E; e++) { pe[e] = expf(acc[e] - l0); s += pe[e]; }
        float p0 = pe[e0] / s, p1 = pe[e1] / s;
        float inv = 1.f / (p0 + p1);
        float w0 = p0 * inv, w1 = p1 * inv;

        int pos0 = atomicAdd(&g_counts[e0], 1);
        g_list[e0 * T_MAX + pos0] = (t << 1) | 0;
        g_wts[(t << 1) | 0] = w0;
        int pos1 = atomicAdd(&g_counts[e1], 1);
        g_list[e1 * T_MAX + pos1] = (t << 1) | 1;
        g_wts[(t << 1) | 1] = w1;
    }
}

__global__ void k_base() {
    if (threadIdx.x == 0 && blockIdx.x == 0) {
        int s = 0;
#pragma unroll
        for (int e = 0; e < E; e++) { g_base[e] = s; s += g_counts[e]; }
    }
}

// Fused up-projection: for expert e's tokens, act = silu(x@w1[e]^T) * (x@w3[e]^T).
// Grid: x = FF/BN, y = T_MAX/BM (early exit beyond count), z = expert.
__global__ __launch_bounds__(256) void k_gemm13(const float* __restrict__ x,
                                                const float* __restrict__ w1,
                                                const float* __restrict__ w3) {
    int e = blockIdx.z;
    int cnt = g_counts[e];
    int row0 = blockIdx.y * BM;
    if (row0 >= cnt) return;
    int n0 = blockIdx.x * BN;

    const float* W1 = w1 + (size_t)e * FF * H + (size_t)n0 * H;
    const float* W3 = w3 + (size_t)e * FF * H + (size_t)n0 * H;

    __shared__ __align__(16) float sA[BK][BM + 4];
    __shared__ __align__(16) float sB1[BK][BN + 4];
    __shared__ __align__(16) float sB3[BK][BN + 4];
    __shared__ int sTok[BM];

    for (int r = threadIdx.x; r < BM; r += 256)
        sTok[r] = (row0 + r < cnt) ? (g_list[e * T_MAX + row0 + r] >> 1) : -1;
    __syncthreads();

    int tid = threadIdx.x;
    int tx = tid & 15;   // 16 column groups of 4
    int ty = tid >> 4;   // 16 row groups of 8

    float acc1[8][4], acc3[8][4];
#pragma unroll
    for (int m = 0; m < 8; m++)
#pragma unroll
        for (int n = 0; n < 4; n++) { acc1[m][n] = 0.f; acc3[m][n] = 0.f; }

    for (int k0 = 0; k0 < H; k0 += BK) {
        // A: 128x16 (gathered rows), 8 elems/thread
#pragma unroll
        for (int i = 0; i < 8; i++) {
            int idx = i * 256 + tid;
            int r = idx >> 4, k = idx & 15;
            int tok = sTok[r];
            sA[k][r] = (tok >= 0) ? x[(size_t)tok * H + k0 + k] : 0.f;
        }
        // B1/B3: 64x16 each, 4 elems/thread each
#pragma unroll
        for (int i = 0; i < 4; i++) {
            int idx = i * 256 + tid;
            int r = idx >> 4, k = idx & 15;
            sB1[k][r] = W1[(size_t)r * H + k0 + k];
            sB3[k][r] = W3[(size_t)r * H + k0 + k];
        }
        __syncthreads();

#pragma unroll
        for (int kk = 0; kk < BK; kk++) {
            float4 a0 = *(const float4*)(&sA[kk][ty * 8]);
            float4 a1 = *(const float4*)(&sA[kk][ty * 8 + 4]);
            float4 b1 = *(const float4*)(&sB1[kk][tx * 4]);
            float4 b3 = *(const float4*)(&sB3[kk][tx * 4]);
            float a[8] = {a0.x, a0.y, a0.z, a0.w, a1.x, a1.y, a1.z, a1.w};
            float v1[4] = {b1.x, b1.y, b1.z, b1.w};
            float v3[4] = {b3.x, b3.y, b3.z, b3.w};
#pragma unroll
            for (int m = 0; m < 8; m++) {
#pragma unroll
                for (int n = 0; n < 4; n++) {
                    acc1[m][n] += a[m] * v1[n];
                    acc3[m][n] += a[m] * v3[n];
                }
            }
        }
        __syncthreads();
    }

    int base = g_base[e];
#pragma unroll
    for (int m = 0; m < 8; m++) {
        int r = ty * 8 + m;
        if (row0 + r < cnt) {
            size_t arow = (size_t)(base + row0 + r) * FF;
            float o[4];
#pragma unroll
            for (int n = 0; n < 4; n++) {
                float h1 = acc1[m][n];
                float sgm = 1.f / (1.f + expf(-h1));
                o[n] = (h1 * sgm) * acc3[m][n];
            }
            *(float4*)&g_act[arow + n0 + tx * 4] = make_float4(o[0], o[1], o[2], o[3]);
        }
    }
}

// Down-projection: y = act @ w2[e]^T, pre-scaled by combine weight, written to (token, slot).
__global__ __launch_bounds__(256) void k_gemm2(const float* __restrict__ w2) {
    int e = blockIdx.z;
    int cnt = g_counts[e];
    int row0 = blockIdx.y * BM;
    if (row0 >= cnt) return;
    int n0 = blockIdx.x * BN;   // over H
    int base = g_base[e];

    const float* W2 = w2 + (size_t)e * H * FF + (size_t)n0 * FF;
    const float* A = g_act + (size_t)base * FF;

    __shared__ __align__(16) float sA[BK][BM + 4];
    __shared__ __align__(16) float sB[BK][BN + 4];

    int tid = threadIdx.x;
    int tx = tid & 15;
    int ty = tid >> 4;

    float acc[8][4];
#pragma unroll
    for (int m = 0; m < 8; m++)
#pragma unroll
        for (int n = 0; n < 4; n++) acc[m][n] = 0.f;

    for (int k0 = 0; k0 < FF; k0 += BK) {
#pragma unroll
        for (int i = 0; i < 8; i++) {
            int idx = i * 256 + tid;
            int r = idx >> 4, k = idx & 15;
            sA[k][r] = (row0 + r < cnt) ? A[(size_t)(row0 + r) * FF + k0 + k] : 0.f;
        }
#pragma unroll
        for (int i = 0; i < 4; i++) {
            int idx = i * 256 + tid;
            int r = idx >> 4, k = idx & 15;
            sB[k][r] = W2[(size_t)r * FF + k0 + k];
        }
        __syncthreads();

#pragma unroll
        for (int kk = 0; kk < BK; kk++) {
            float4 a0 = *(const float4*)(&sA[kk][ty * 8]);
            float4 a1 = *(const float4*)(&sA[kk][ty * 8 + 4]);
            float4 bv = *(const float4*)(&sB[kk][tx * 4]);
            float a[8] = {a0.x, a0.y, a0.z, a0.w, a1.x, a1.y, a1.z, a1.w};
            float b[4] = {bv.x, bv.y, bv.z, bv.w};
#pragma unroll
            for (int m = 0; m < 8; m++)
#pragma unroll
                for (int n = 0; n < 4; n++) acc[m][n] += a[m] * b[n];
        }
        __syncthreads();
    }

#pragma unroll
    for (int m = 0; m < 8; m++) {
        int r = ty * 8 + m;
        if (row0 + r < cnt) {
            int ts = g_list[e * T_MAX + row0 + r];
            float w = g_wts[ts];
            size_t yrow = (size_t)ts * H;
            float o[4];
#pragma unroll
            for (int n = 0; n < 4; n++) o[n] = w * acc[m][n];
            *(float4*)&g_ybuf[yrow + n0 + tx * 4] = make_float4(o[0], o[1], o[2], o[3]);
        }
    }
}

// out[t, h] = ybuf[t, slot0, h] + ybuf[t, slot1, h]
__global__ void k_combine(float* __restrict__ out, int T) {
    int i = blockIdx.x * blockDim.x + threadIdx.x;     // over T*H/4
    int total = T * (H / 4);
    if (i >= total) return;
    int t = i / (H / 4);
    int h4 = i - t * (H / 4);
    const float4* yb = (const float4*)g_ybuf;
    float4 a = yb[(size_t)(2 * t) * (H / 4) + h4];
    float4 b = yb[(size_t)(2 * t + 1) * (H / 4) + h4];
    ((float4*)out)[i] = make_float4(a.x + b.x, a.y + b.y, a.z + b.z, a.w + b.w);
}

// ---------------- launch ----------------
extern "C" void kernel_launch(void* const* d_in, const int* in_sizes, int n_in,
                              void* d_out, int out_size) {
    // Inputs: hidden_states, gate_w, w1, w2, w3 (guard against gate/hidden swap by size)
    const float* x;
    const float* gate;
    if (in_sizes[0] > in_sizes[1]) { x = (const float*)d_in[0]; gate = (const float*)d_in[1]; }
    else                           { gate = (const float*)d_in[0]; x = (const float*)d_in[1]; }
    const float* w1 = (const float*)d_in[2];
    const float* w2 = (const float*)d_in[3];
    const float* w3 = (const float*)d_in[4];

    int T = (in_sizes[0] > in_sizes[1] ? in_sizes[0] : in_sizes[1]) / H;

    float* out = (float*)d_out;
    float* logits_out = out + (size_t)T * H;   // router_logits appended after moe output

    k_zero<<<1, 32>>>();
    k_router<<<(T + 7) / 8, 256>>>(x, gate, logits_out, T);
    k_base<<<1, 1>>>();

    dim3 g13(FF / BN, (T + BM - 1) / BM, E);
    k_gemm13<<<g13, 256>>>(x, w1, w3);

    dim3 g2(H / BN, (T + BM - 1) / BM, E);
    k_gemm2<<<g2, 256>>>(w2);

    int n4 = T * (H / 4);
    k_combine<<<(n4 + 255) / 256, 256>>>(out, T);
}

// round 5
// speedup vs baseline: 7.2297x; 7.2297x over previous
#include <cuda_runtime.h>
#include <cuda_bf16.h>
#include <cstdint>
#include <stdint.h>
#include <math.h>

#define H     1024
#define FF    4096
#define E     8
#define T_MAX 8192
#define NROWS (T_MAX * 2)
#define TILE_B 16384  // 128 rows x 128 bytes (64 bf16)

#if defined(__CUDA_ARCH_FEAT_SM103_ALL) || defined(__CUDA_ARCH_FEAT_SM100_ALL)
#define TC_OK 1
#else
#define TC_OK 0
#endif

// ---------------- device scratch ----------------
__device__ int   g_use_tc;
__device__ int   g_counts[E];
__device__ int   g_base[E];
__device__ int   g_list[E * T_MAX];
__device__ float g_wts[T_MAX * 2];
__device__ __nv_bfloat16 g_ax_hi[(size_t)NROWS * H];
__device__ __nv_bfloat16 g_ax_lo[(size_t)NROWS * H];
__device__ __nv_bfloat16 g_w1h[(size_t)E * FF * H];
__device__ __nv_bfloat16 g_w1l[(size_t)E * FF * H];
__device__ __nv_bfloat16 g_w3h[(size_t)E * FF * H];
__device__ __nv_bfloat16 g_w3l[(size_t)E * FF * H];
__device__ __nv_bfloat16 g_w2h[(size_t)E * H * FF];
__device__ __nv_bfloat16 g_w2l[(size_t)E * H * FF];
__device__ __nv_bfloat16 g_act_hi[(size_t)NROWS * FF];
__device__ __nv_bfloat16 g_act_lo[(size_t)NROWS * FF];
__device__ float g_actf[(size_t)NROWS * FF];   // fp32 act for fallback path
__device__ float g_ybuf[(size_t)NROWS * H];

// ---------------- PTX helpers ----------------
__device__ __forceinline__ uint32_t smem_u32(const void* p) {
    uint32_t a;
    asm("{ .reg .u64 t; cvta.to.shared.u64 t, %1; cvt.u32.u64 %0, t; }" : "=r"(a) : "l"(p));
    return a;
}
#define MBAR_INIT(a, c) asm volatile("mbarrier.init.shared.b64 [%0], %1;" :: "r"((uint32_t)(a)), "r"((uint32_t)(c)) : "memory")
#define MBAR_WAIT(a, ph) do { \
    uint32_t _m = (uint32_t)(a), _p = (uint32_t)(ph), _d; \
    asm volatile("{\n\t.reg .pred p;\n\tmbarrier.try_wait.parity.acquire.cta.shared::cta.b64 p, [%1], %2;\n\tselp.b32 %0,1,0,p;\n\t}" \
        : "=r"(_d) : "r"(_m), "r"(_p) : "memory"); \
    if (!_d) { asm volatile("{\n\t.reg .pred P1;\n\tWL_%=:\n\t" \
        "mbarrier.try_wait.parity.acquire.cta.shared::cta.b64 P1, [%0], %1, 0x989680;\n\t" \
        "@P1 bra.uni WD_%=;\n\tbra.uni WL_%=;\n\tWD_%=:\n\t}" :: "r"(_m), "r"(_p) : "memory"); } \
} while (0)

#if TC_OK
#define TC_ALLOC(sa, n)   asm volatile("tcgen05.alloc.cta_group::1.sync.aligned.shared::cta.b32 [%0], %1;" :: "r"((uint32_t)(sa)), "r"((uint32_t)(n)) : "memory")
#define TC_DEALLOC(tm, n) asm volatile("tcgen05.dealloc.cta_group::1.sync.aligned.b32 %0, %1;" :: "r"(tm), "r"((uint32_t)(n)))
#define TC_RELINQ()       asm volatile("tcgen05.relinquish_alloc_permit.cta_group::1.sync.aligned;")
#define TC_COMMIT(mb)     asm volatile("tcgen05.commit.cta_group::1.mbarrier::arrive::one.shared::cluster.b64 [%0];" :: "r"((uint32_t)(mb)) : "memory")
#define TC_FENCE_AFTER()  asm volatile("tcgen05.fence::after_thread_sync;" ::: "memory")
#define TC_FENCE_BEFORE() asm volatile("tcgen05.fence::before_thread_sync;" ::: "memory")
#define TC_WAIT_LD()      asm volatile("tcgen05.wait::ld.sync.aligned;" ::: "memory")
#define FENCE_ASYNC()     asm volatile("fence.proxy.async.shared::cta;" ::: "memory")
#define TC_LD_X32(r, ta) \
    asm volatile("tcgen05.ld.sync.aligned.32x32b.x32.b32 " \
        "{%0,%1,%2,%3,%4,%5,%6,%7,%8,%9,%10,%11,%12,%13,%14,%15," \
        "%16,%17,%18,%19,%20,%21,%22,%23,%24,%25,%26,%27,%28,%29,%30,%31}, [%32];" \
        : "=r"((r)[0]), "=r"((r)[1]), "=r"((r)[2]), "=r"((r)[3]), "=r"((r)[4]), "=r"((r)[5]), "=r"((r)[6]), "=r"((r)[7]), \
          "=r"((r)[8]), "=r"((r)[9]), "=r"((r)[10]), "=r"((r)[11]), "=r"((r)[12]), "=r"((r)[13]), "=r"((r)[14]), "=r"((r)[15]), \
          "=r"((r)[16]), "=r"((r)[17]), "=r"((r)[18]), "=r"((r)[19]), "=r"((r)[20]), "=r"((r)[21]), "=r"((r)[22]), "=r"((r)[23]), \
          "=r"((r)[24]), "=r"((r)[25]), "=r"((r)[26]), "=r"((r)[27]), "=r"((r)[28]), "=r"((r)[29]), "=r"((r)[30]), "=r"((r)[31]) \
        : "r"(ta))

static constexpr uint64_t DESC_BASE =
    (uint64_t(2) << 61) | (uint64_t(1) << 46) | (uint64_t(64) << 32) | (uint64_t(1) << 16);
#define MK_DESC(a) (DESC_BASE | ((uint64_t)((a) >> 4) & 0x3FFF))
// idesc kind::f16: F32 out, BF16 a/b, N=128, M=128
#define IDESC ((1u << 4) | (1u << 7) | (1u << 10) | (16u << 17) | (8u << 24))

__device__ __forceinline__ void mma_ss(uint32_t d, uint64_t a, uint64_t b, uint32_t en) {
    asm volatile("{\n\t.reg .pred p;\n\tsetp.ne.u32 p, %4, 0;\n\t"
        "tcgen05.mma.cta_group::1.kind::f16 [%0], %1, %2, %3, {%5,%5,%5,%5}, p;\n\t}"
        :: "r"(d), "l"(a), "l"(b), "r"(IDESC), "r"(en), "r"(0u) : "memory");
}
#endif  // TC_OK

__device__ __forceinline__ uint32_t pack_hi(float a, float b, uint32_t& lo) {
    __nv_bfloat16 h0 = __float2bfloat16(a), h1 = __float2bfloat16(b);
    __nv_bfloat16 l0 = __float2bfloat16(a - __bfloat162float(h0));
    __nv_bfloat16 l1 = __float2bfloat16(b - __bfloat162float(h1));
    lo = (uint32_t)__bfloat16_as_ushort(l0) | ((uint32_t)__bfloat16_as_ushort(l1) << 16);
    return (uint32_t)__bfloat16_as_ushort(h0) | ((uint32_t)__bfloat16_as_ushort(h1) << 16);
}

// ---------------- probe ----------------
__global__ void k_probe() {
    if (threadIdx.x == 0) g_use_tc = TC_OK;
}

// ---------------- routing ----------------
__global__ void k_zero() { if (threadIdx.x < E) g_counts[threadIdx.x] = 0; }

__global__ void k_router(const float* __restrict__ x, const float* __restrict__ gate,
                         float* __restrict__ logits_out, int T) {
    __shared__ float sg[E * H];
    for (int i = threadIdx.x; i < E * H; i += blockDim.x) sg[i] = gate[i];
    __syncthreads();
    int warp = threadIdx.x >> 5, lane = threadIdx.x & 31;
    int t = blockIdx.x * 8 + warp;
    if (t >= T) return;
    const float* xr = x + (size_t)t * H;
    float acc[E];
#pragma unroll
    for (int e = 0; e < E; e++) acc[e] = 0.f;
    for (int k = lane; k < H; k += 32) {
        float xv = xr[k];
#pragma unroll
        for (int e = 0; e < E; e++) acc[e] += xv * sg[e * H + k];
    }
#pragma unroll
    for (int e = 0; e < E; e++)
#pragma unroll
        for (int o = 16; o > 0; o >>= 1) acc[e] += __shfl_down_sync(0xffffffffu, acc[e], o);
    if (lane == 0) {
#pragma unroll
        for (int e = 0; e < E; e++) logits_out[(size_t)t * E + e] = acc[e];
        int e0 = 0; float l0 = acc[0];
#pragma unroll
        for (int e = 1; e < E; e++) if (acc[e] > l0) { l0 = acc[e]; e0 = e; }
        int e1 = -1; float l1 = -1e30f;
#pragma unroll
        for (int e = 0; e < E; e++) if (e != e0 && acc[e] > l1) { l1 = acc[e]; e1 = e; }
        float s = 0.f, pe[E];
#pragma unroll
        for (int e = 0; e < E; e++) { pe[e] = expf(acc[e] - l0); s += pe[e]; }
        float p0 = pe[e0] / s, p1 = pe[e1] / s;
        float inv = 1.f / (p0 + p1);
        int q0 = atomicAdd(&g_counts[e0], 1);
        g_list[e0 * T_MAX + q0] = (t << 1);
        g_wts[(t << 1)] = p0 * inv;
        int q1 = atomicAdd(&g_counts[e1], 1);
        g_list[e1 * T_MAX + q1] = (t << 1) | 1;
        g_wts[(t << 1) | 1] = p1 * inv;
    }
}

__global__ void k_base() {
    if (threadIdx.x == 0) {
        int s = 0;
#pragma unroll
        for (int e = 0; e < E; e++) { g_base[e] = s; s += g_counts[e]; }
    }
}

// fp32 -> bf16 hi/lo (8 elems/thread); only needed for tc path
__global__ void k_split8(const float* __restrict__ src, __nv_bfloat16* __restrict__ hi,
                         __nv_bfloat16* __restrict__ lo, long n8) {
    if (!g_use_tc) return;
    long i = (long)blockIdx.x * blockDim.x + threadIdx.x;
    if (i >= n8) return;
    const float4* s4 = (const float4*)src;
    float4 a = s4[2 * i], b = s4[2 * i + 1];
    float v[8] = {a.x, a.y, a.z, a.w, b.x, b.y, b.z, b.w};
    uint32_t ph[4], pl[4];
#pragma unroll
    for (int j = 0; j < 4; j++) ph[j] = pack_hi(v[2 * j], v[2 * j + 1], pl[j]);
    ((uint4*)hi)[i] = make_uint4(ph[0], ph[1], ph[2], ph[3]);
    ((uint4*)lo)[i] = make_uint4(pl[0], pl[1], pl[2], pl[3]);
}

// gather x rows into expert-grouped hi/lo
__global__ void k_gather(const float* __restrict__ x, int total) {
    if (!g_use_tc) return;
    int g = blockIdx.x;
    if (g >= total) return;
    int e = 0;
#pragma unroll
    for (int k = 1; k < E; k++) if (g >= g_base[k]) e = k;
    int tok = g_list[e * T_MAX + (g - g_base[e])] >> 1;
    const float4* src = (const float4*)(x + (size_t)tok * H);
    uint2* dh = (uint2*)(g_ax_hi + (size_t)g * H);
    uint2* dl = (uint2*)(g_ax_lo + (size_t)g * H);
    for (int i = threadIdx.x; i < H / 4; i += blockDim.x) {
        float4 v = src[i];
        uint32_t l0, l1;
        uint32_t h0 = pack_hi(v.x, v.y, l0);
        uint32_t h1 = pack_hi(v.z, v.w, l1);
        dh[i] = make_uint2(h0, h1);
        dl[i] = make_uint2(l0, l1);
    }
}

// ---------------- shared tile loader (SW128 swizzle) ----------------
__device__ __forceinline__ void load_tile(char* sm, uint32_t off, const __nv_bfloat16* src,
                                          int rbase, int rmax, int K, int k0, int tid) {
#pragma unroll
    for (int j = 0; j < 8; j++) {
        int idx = j * 128 + tid;
        int r = idx >> 3, c = idx & 7;
        int row = rbase + r; if (row > rmax) row = rmax;
        uint4 v = ((const uint4*)(src + (size_t)row * K))[(k0 >> 3) + c];
        *(uint4*)(sm + off + (r << 7) + ((c ^ (r & 7)) << 4)) = v;
    }
}

#define SM_TILES 1024

// ---------------- tcgen05 GEMM13 ----------------
__global__ __launch_bounds__(128, 1) void k_mma13() {
#if TC_OK
    int e = blockIdx.z;
    int cnt = g_counts[e];
    int row0 = blockIdx.y * 128;
    if (row0 >= cnt) return;
    int n0 = blockIdx.x * 128;
    int grow0 = g_base[e] + row0;
    int wrow0 = e * FF + n0;

    extern __shared__ char sm[];
    uint32_t sb = smem_u32(sm);
    int tid = threadIdx.x, wid = tid >> 5, lid = tid & 31;

    if (wid == 0) TC_ALLOC(sb, 256);
    if (tid == 0) { MBAR_INIT(sb + 8, 1); MBAR_INIT(sb + 16, 1); }
    __syncthreads();
    uint32_t tm;
    asm volatile("ld.shared.b32 %0, [%1];" : "=r"(tm) : "r"(sb));

    load_tile(sm, SM_TILES + 0 * TILE_B, g_ax_hi, grow0, NROWS - 1, H, 0, tid);
    load_tile(sm, SM_TILES + 1 * TILE_B, g_ax_lo, grow0, NROWS - 1, H, 0, tid);
    load_tile(sm, SM_TILES + 2 * TILE_B, g_w1h, wrow0, E * FF - 1, H, 0, tid);
    load_tile(sm, SM_TILES + 3 * TILE_B, g_w1l, wrow0, E * FF - 1, H, 0, tid);
    load_tile(sm, SM_TILES + 4 * TILE_B, g_w3h, wrow0, E * FF - 1, H, 0, tid);
    load_tile(sm, SM_TILES + 5 * TILE_B, g_w3l, wrow0, E * FF - 1, H, 0, tid);
    __syncthreads();

    uint32_t en1 = 0, en3 = 0;
    int w0 = 0, w1c = 0;
    const int NCH = H / 64;  // 16
    for (int i = 0; i < NCH; i++) {
        int buf = i & 1;
        if (tid == 0) {
            FENCE_ASYNC();
            TC_FENCE_AFTER();
            uint32_t tb = sb + SM_TILES + buf * 6 * TILE_B;
            uint64_t dAh = MK_DESC(tb), dAl = MK_DESC(tb + TILE_B);
            uint64_t d1h = MK_DESC(tb + 2 * TILE_B), d1l = MK_DESC(tb + 3 * TILE_B);
            uint64_t d3h = MK_DESC(tb + 4 * TILE_B), d3l = MK_DESC(tb + 5 * TILE_B);
#pragma unroll
            for (int s = 0; s < 4; s++) {
                uint64_t o = (uint64_t)(2 * s);
                mma_ss(tm,       dAh + o, d1h + o, en1); en1 = 1;
                mma_ss(tm,       dAh + o, d1l + o, 1);
                mma_ss(tm,       dAl + o, d1h + o, 1);
                mma_ss(tm + 128, dAh + o, d3h + o, en3); en3 = 1;
                mma_ss(tm + 128, dAh + o, d3l + o, 1);
                mma_ss(tm + 128, dAl + o, d3h + o, 1);
            }
            TC_COMMIT(sb + 8 + buf * 8);
        }
        if (i + 1 < NCH) {
            int nb = (i + 1) & 1;
            if (i >= 1) {
                if (nb == 0) { MBAR_WAIT(sb + 8, w0 & 1); w0++; }
                else         { MBAR_WAIT(sb + 16, w1c & 1); w1c++; }
            }
            int k0 = (i + 1) * 64;
            uint32_t o = SM_TILES + nb * 6 * TILE_B;
            load_tile(sm, o + 0 * TILE_B, g_ax_hi, grow0, NROWS - 1, H, k0, tid);
            load_tile(sm, o + 1 * TILE_B, g_ax_lo, grow0, NROWS - 1, H, k0, tid);
            load_tile(sm, o + 2 * TILE_B, g_w1h, wrow0, E * FF - 1, H, k0, tid);
            load_tile(sm, o + 3 * TILE_B, g_w1l, wrow0, E * FF - 1, H, k0, tid);
            load_tile(sm, o + 4 * TILE_B, g_w3h, wrow0, E * FF - 1, H, k0, tid);
            load_tile(sm, o + 5 * TILE_B, g_w3l, wrow0, E * FF - 1, H, k0, tid);
            __syncthreads();
        }
    }
    MBAR_WAIT(sb + 8, w0 & 1);
    MBAR_WAIT(sb + 16, w1c & 1);
    TC_FENCE_AFTER();

    int rloc = wid * 32 + lid;
    bool valid = (row0 + rloc) < cnt;
    size_t arow = (size_t)(grow0 + rloc) * FF + n0;
#pragma unroll
    for (int c0 = 0; c0 < 128; c0 += 32) {
        uint32_t d1[32], d3[32];
        TC_LD_X32(d1, tm + c0);
        TC_LD_X32(d3, tm + 128 + c0);
        TC_WAIT_LD();
        if (valid) {
            uint32_t ph[16], pl[16];
#pragma unroll
            for (int j = 0; j < 16; j++) {
                float h0 = __uint_as_float(d1[2 * j]),     v0 = __uint_as_float(d3[2 * j]);
                float h1 = __uint_as_float(d1[2 * j + 1]), v1 = __uint_as_float(d3[2 * j + 1]);
                float a0 = (h0 / (1.f + __expf(-h0))) * v0;
                float a1 = (h1 / (1.f + __expf(-h1))) * v1;
                ph[j] = pack_hi(a0, a1, pl[j]);
            }
            uint4* dh = (uint4*)(g_act_hi + arow + c0);
            uint4* dl = (uint4*)(g_act_lo + arow + c0);
#pragma unroll
            for (int q = 0; q < 4; q++) {
                dh[q] = make_uint4(ph[4 * q], ph[4 * q + 1], ph[4 * q + 2], ph[4 * q + 3]);
                dl[q] = make_uint4(pl[4 * q], pl[4 * q + 1], pl[4 * q + 2], pl[4 * q + 3]);
            }
        }
    }
    TC_FENCE_BEFORE();
    __syncthreads();
    if (wid == 0) { TC_RELINQ(); TC_DEALLOC(tm, 256); }
#endif
}

// ---------------- tcgen05 GEMM2 ----------------
__global__ __launch_bounds__(128, 1) void k_mma2() {
#if TC_OK
    int e = blockIdx.z;
    int cnt = g_counts[e];
    int row0 = blockIdx.y * 128;
    if (row0 >= cnt) return;
    int n0 = blockIdx.x * 128;
    int grow0 = g_base[e] + row0;
    int wrow0 = e * H + n0;

    extern __shared__ char sm[];
    uint32_t sb = smem_u32(sm);
    int tid = threadIdx.x, wid = tid >> 5, lid = tid & 31;

    if (wid == 0) TC_ALLOC(sb, 128);
    if (tid == 0) { MBAR_INIT(sb + 8, 1); MBAR_INIT(sb + 16, 1); }
    __syncthreads();
    uint32_t tm;
    asm volatile("ld.shared.b32 %0, [%1];" : "=r"(tm) : "r"(sb));

    load_tile(sm, SM_TILES + 0 * TILE_B, g_act_hi, grow0, NROWS - 1, FF, 0, tid);
    load_tile(sm, SM_TILES + 1 * TILE_B, g_act_lo, grow0, NROWS - 1, FF, 0, tid);
    load_tile(sm, SM_TILES + 2 * TILE_B, g_w2h, wrow0, E * H - 1, FF, 0, tid);
    load_tile(sm, SM_TILES + 3 * TILE_B, g_w2l, wrow0, E * H - 1, FF, 0, tid);
    __syncthreads();

    uint32_t en = 0;
    int w0 = 0, w1c = 0;
    const int NCH = FF / 64;  // 64
    for (int i = 0; i < NCH; i++) {
        int buf = i & 1;
        if (tid == 0) {
            FENCE_ASYNC();
            TC_FENCE_AFTER();
            uint32_t tb = sb + SM_TILES + buf * 4 * TILE_B;
            uint64_t dAh = MK_DESC(tb), dAl = MK_DESC(tb + TILE_B);
            uint64_t dWh = MK_DESC(tb + 2 * TILE_B), dWl = MK_DESC(tb + 3 * TILE_B);
#pragma unroll
            for (int s = 0; s < 4; s++) {
                uint64_t o = (uint64_t)(2 * s);
                mma_ss(tm, dAh + o, dWh + o, en); en = 1;
                mma_ss(tm, dAh + o, dWl + o, 1);
                mma_ss(tm, dAl + o, dWh + o, 1);
            }
            TC_COMMIT(sb + 8 + buf * 8);
        }
        if (i + 1 < NCH) {
            int nb = (i + 1) & 1;
            if (i >= 1) {
                if (nb == 0) { MBAR_WAIT(sb + 8, w0 & 1); w0++; }
                else         { MBAR_WAIT(sb + 16, w1c & 1); w1c++; }
            }
            int k0 = (i + 1) * 64;
            uint32_t o = SM_TILES + nb * 4 * TILE_B;
            load_tile(sm, o + 0 * TILE_B, g_act_hi, grow0, NROWS - 1, FF, k0, tid);
            load_tile(sm, o + 1 * TILE_B, g_act_lo, grow0, NROWS - 1, FF, k0, tid);
            load_tile(sm, o + 2 * TILE_B, g_w2h, wrow0, E * H - 1, FF, k0, tid);
            load_tile(sm, o + 3 * TILE_B, g_w2l, wrow0, E * H - 1, FF, k0, tid);
            __syncthreads();
        }
    }
    MBAR_WAIT(sb + 8, w0 & 1);
    MBAR_WAIT(sb + 16, w1c & 1);
    TC_FENCE_AFTER();

    int rloc = wid * 32 + lid;
    bool valid = (row0 + rloc) < cnt;
    int ts = 0; float w = 0.f;
    if (valid) { ts = g_list[e * T_MAX + row0 + rloc]; w = g_wts[ts]; }
    float* yrow = g_ybuf + (size_t)ts * H + n0;
#pragma unroll
    for (int c0 = 0; c0 < 128; c0 += 32) {
        uint32_t d[32];
        TC_LD_X32(d, tm + c0);
        TC_WAIT_LD();
        if (valid) {
            float4* dst = (float4*)(yrow + c0);
#pragma unroll
            for (int q = 0; q < 8; q++)
                dst[q] = make_float4(w * __uint_as_float(d[4 * q]), w * __uint_as_float(d[4 * q + 1]),
                                     w * __uint_as_float(d[4 * q + 2]), w * __uint_as_float(d[4 * q + 3]));
        }
    }
    TC_FENCE_BEFORE();
    __syncthreads();
    if (wid == 0) { TC_RELINQ(); TC_DEALLOC(tm, 128); }
#endif
}

// ---------------- SIMT fallback GEMMs (round-1, run only if !g_use_tc) ----------------
#define BM 128
#define BN 64
#define BK 16

__global__ __launch_bounds__(256) void k_gemm13f(const float* __restrict__ x,
                                                 const float* __restrict__ w1,
                                                 const float* __restrict__ w3) {
    if (g_use_tc) return;
    int e = blockIdx.z;
    int cnt = g_counts[e];
    int row0 = blockIdx.y * BM;
    if (row0 >= cnt) return;
    int n0 = blockIdx.x * BN;
    const float* W1 = w1 + (size_t)e * FF * H + (size_t)n0 * H;
    const float* W3 = w3 + (size_t)e * FF * H + (size_t)n0 * H;
    __shared__ __align__(16) float sA[BK][BM + 4];
    __shared__ __align__(16) float sB1[BK][BN + 4];
    __shared__ __align__(16) float sB3[BK][BN + 4];
    __shared__ int sTok[BM];
    for (int r = threadIdx.x; r < BM; r += 256)
        sTok[r] = (row0 + r < cnt) ? (g_list[e * T_MAX + row0 + r] >> 1) : -1;
    __syncthreads();
    int tid = threadIdx.x, tx = tid & 15, ty = tid >> 4;
    float acc1[8][4], acc3[8][4];
#pragma unroll
    for (int m = 0; m < 8; m++)
#pragma unroll
        for (int n = 0; n < 4; n++) { acc1[m][n] = 0.f; acc3[m][n] = 0.f; }
    for (int k0 = 0; k0 < H; k0 += BK) {
#pragma unroll
        for (int i = 0; i < 8; i++) {
            int idx = i * 256 + tid, r = idx >> 4, k = idx & 15;
            int tok = sTok[r];
            sA[k][r] = (tok >= 0) ? x[(size_t)tok * H + k0 + k] : 0.f;
        }
#pragma unroll
        for (int i = 0; i < 4; i++) {
            int idx = i * 256 + tid, r = idx >> 4, k = idx & 15;
            sB1[k][r] = W1[(size_t)r * H + k0 + k];
            sB3[k][r] = W3[(size_t)r * H + k0 + k];
        }
        __syncthreads();
#pragma unroll
        for (int kk = 0; kk < BK; kk++) {
            float4 a0 = *(const float4*)(&sA[kk][ty * 8]);
            float4 a1 = *(const float4*)(&sA[kk][ty * 8 + 4]);
            float4 b1 = *(const float4*)(&sB1[kk][tx * 4]);
            float4 b3 = *(const float4*)(&sB3[kk][tx * 4]);
            float a[8] = {a0.x, a0.y, a0.z, a0.w, a1.x, a1.y, a1.z, a1.w};
            float v1[4] = {b1.x, b1.y, b1.z, b1.w};
            float v3[4] = {b3.x, b3.y, b3.z, b3.w};
#pragma unroll
            for (int m = 0; m < 8; m++)
#pragma unroll
                for (int n = 0; n < 4; n++) { acc1[m][n] += a[m] * v1[n]; acc3[m][n] += a[m] * v3[n]; }
        }
        __syncthreads();
    }
    int base = g_base[e];
#pragma unroll
    for (int m = 0; m < 8; m++) {
        int r = ty * 8 + m;
        if (row0 + r < cnt) {
            size_t arow = (size_t)(base + row0 + r) * FF;
            float o[4];
#pragma unroll
            for (int n = 0; n < 4; n++) {
                float h1 = acc1[m][n];
                o[n] = (h1 / (1.f + expf(-h1))) * acc3[m][n];
            }
            *(float4*)&g_actf[arow + n0 + tx * 4] = make_float4(o[0], o[1], o[2], o[3]);
        }
    }
}

__global__ __launch_bounds__(256) void k_gemm2f(const float* __restrict__ w2) {
    if (g_use_tc) return;
    int e = blockIdx.z;
    int cnt = g_counts[e];
    int row0 = blockIdx.y * BM;
    if (row0 >= cnt) return;
    int n0 = blockIdx.x * BN;
    int base = g_base[e];
    const float* W2 = w2 + (size_t)e * H * FF + (size_t)n0 * FF;
    const float* A = g_actf + (size_t)base * FF;
    __shared__ __align__(16) float sA[BK][BM + 4];
    __shared__ __align__(16) float sB[BK][BN + 4];
    int tid = threadIdx.x, tx = tid & 15, ty = tid >> 4;
    float acc[8][4];
#pragma unroll
    for (int m = 0; m < 8; m++)
#pragma unroll
        for (int n = 0; n < 4; n++) acc[m][n] = 0.f;
    for (int k0 = 0; k0 < FF; k0 += BK) {
#pragma unroll
        for (int i = 0; i < 8; i++) {
            int idx = i * 256 + tid, r = idx >> 4, k = idx & 15;
            sA[k][r] = (row0 + r < cnt) ? A[(size_t)(row0 + r) * FF + k0 + k] : 0.f;
        }
#pragma unroll
        for (int i = 0; i < 4; i++) {
            int idx = i * 256 + tid, r = idx >> 4, k = idx & 15;
            sB[k][r] = W2[(size_t)r * FF + k0 + k];
        }
        __syncthreads();
#pragma unroll
        for (int kk = 0; kk < BK; kk++) {
            float4 a0 = *(const float4*)(&sA[kk][ty * 8]);
            float4 a1 = *(const float4*)(&sA[kk][ty * 8 + 4]);
            float4 bv = *(const float4*)(&sB[kk][tx * 4]);
            float a[8] = {a0.x, a0.y, a0.z, a0.w, a1.x, a1.y, a1.z, a1.w};
            float b[4] = {bv.x, bv.y, bv.z, bv.w};
#pragma unroll
            for (int m = 0; m < 8; m++)
#pragma unroll
                for (int n = 0; n < 4; n++) acc[m][n] += a[m] * b[n];
        }
        __syncthreads();
    }
#pragma unroll
    for (int m = 0; m < 8; m++) {
        int r = ty * 8 + m;
        if (row0 + r < cnt) {
            int ts = g_list[e * T_MAX + row0 + r];
            float w = g_wts[ts];
            size_t yrow = (size_t)ts * H;
            *(float4*)&g_ybuf[yrow + n0 + tx * 4] =
                make_float4(w * acc[m][0], w * acc[m][1], w * acc[m][2], w * acc[m][3]);
        }
    }
}

__global__ void k_combine(float* __restrict__ out, int T) {
    int i = blockIdx.x * blockDim.x + threadIdx.x;
    int total = T * (H / 4);
    if (i >= total) return;
    int t = i / (H / 4);
    int h4 = i - t * (H / 4);
    const float4* yb = (const float4*)g_ybuf;
    float4 a = yb[(size_t)(2 * t) * (H / 4) + h4];
    float4 b = yb[(size_t)(2 * t + 1) * (H / 4) + h4];
    ((float4*)out)[i] = make_float4(a.x + b.x, a.y + b.y, a.z + b.z, a.w + b.w);
}

// ---------------- launch ----------------
extern "C" void kernel_launch(void* const* d_in, const int* in_sizes, int n_in,
                              void* d_out, int out_size) {
    const float* x;
    const float* gate;
    if (in_sizes[0] > in_sizes[1]) { x = (const float*)d_in[0]; gate = (const float*)d_in[1]; }
    else                           { gate = (const float*)d_in[0]; x = (const float*)d_in[1]; }
    const float* w1 = (const float*)d_in[2];
    const float* w2 = (const float*)d_in[3];
    const float* w3 = (const float*)d_in[4];
    int T = (in_sizes[0] > in_sizes[1] ? in_sizes[0] : in_sizes[1]) / H;

    float* out = (float*)d_out;
    float* logits_out = out + (size_t)T * H;

    int smem13 = SM_TILES + 2 * 6 * TILE_B;  // 197,632
    int smem2  = SM_TILES + 2 * 4 * TILE_B;  // 132,096
    cudaFuncSetAttribute(k_mma13, cudaFuncAttributeMaxDynamicSharedMemorySize, smem13);
    cudaFuncSetAttribute(k_mma2,  cudaFuncAttributeMaxDynamicSharedMemorySize, smem2);

    __nv_bfloat16 *w1h, *w1l, *w3h, *w3l, *w2h, *w2l;
    cudaGetSymbolAddress((void**)&w1h, g_w1h); cudaGetSymbolAddress((void**)&w1l, g_w1l);
    cudaGetSymbolAddress((void**)&w3h, g_w3h); cudaGetSymbolAddress((void**)&w3l, g_w3l);
    cudaGetSymbolAddress((void**)&w2h, g_w2h); cudaGetSymbolAddress((void**)&w2l, g_w2l);

    k_probe<<<1, 32>>>();
    k_zero<<<1, 32>>>();
    k_router<<<(T + 7) / 8, 256>>>(x, gate, logits_out, T);
    k_base<<<1, 1>>>();

    long n8 = (long)E * FF * H / 8;
    int sblk = (int)((n8 + 255) / 256);
    k_split8<<<sblk, 256>>>(w1, w1h, w1l, n8);
    k_split8<<<sblk, 256>>>(w3, w3h, w3l, n8);
    k_split8<<<sblk, 256>>>(w2, w2h, w2l, n8);
    k_gather<<<2 * T, 128>>>(x, 2 * T);

    int ytiles = (T + 127) / 128;
    dim3 g13(FF / 128, ytiles, E);
    k_mma13<<<g13, 128, smem13>>>();
    dim3 g2(H / 128, ytiles, E);
    k_mma2<<<g2, 128, smem2>>>();

    // Fallback path (no-ops when tcgen05 cubin is active)
    dim3 f13(FF / BN, (T * 2 + BM - 1) / BM, E);
    k_gemm13f<<<f13, 256>>>(x, w1, w3);
    dim3 f2(H / BN, (T * 2 + BM - 1) / BM, E);
    k_gemm2f<<<f2, 256>>>(w2);

    k_combine<<<(T * (H / 4) + 255) / 256, 256>>>(out, T);
}

// round 6
// speedup vs baseline: 9.3187x; 1.2890x over previous
#include <cuda_runtime.h>
#include <cuda_bf16.h>
#include <cstdint>
#include <stdint.h>
#include <math.h>

#define H     1024
#define FF    4096
#define E     8
#define T_MAX 8192
#define NROWS (T_MAX * 2)
#define KC    32          // K-chunk
#define TB    8192        // 128 rows x 64 bytes (SW64 tile)

#if defined(__CUDA_ARCH_FEAT_SM103_ALL) || defined(__CUDA_ARCH_FEAT_SM100_ALL)
#define TC_OK 1
#else
#define TC_OK 0
#endif

// ---------------- device scratch ----------------
__device__ int   g_counts[E];
__device__ int   g_base[E];
__device__ int   g_list[E * T_MAX];
__device__ float g_wts[T_MAX * 2];
__device__ __nv_bfloat16 g_ax_hi[(size_t)NROWS * H];
__device__ __nv_bfloat16 g_ax_lo[(size_t)NROWS * H];
__device__ __nv_bfloat16 g_w1h[(size_t)E * FF * H];
__device__ __nv_bfloat16 g_w1l[(size_t)E * FF * H];
__device__ __nv_bfloat16 g_w3h[(size_t)E * FF * H];
__device__ __nv_bfloat16 g_w3l[(size_t)E * FF * H];
__device__ __nv_bfloat16 g_w2h[(size_t)E * H * FF];
__device__ __nv_bfloat16 g_w2l[(size_t)E * H * FF];
__device__ __nv_bfloat16 g_act_hi[(size_t)NROWS * FF];
__device__ __nv_bfloat16 g_act_lo[(size_t)NROWS * FF];
__device__ float g_ybuf[(size_t)NROWS * H];

// ---------------- PTX helpers ----------------
__device__ __forceinline__ uint32_t smem_u32(const void* p) {
    uint32_t a;
    asm("{ .reg .u64 t; cvta.to.shared.u64 t, %1; cvt.u32.u64 %0, t; }" : "=r"(a) : "l"(p));
    return a;
}
#define MBAR_INIT(a, c) asm volatile("mbarrier.init.shared.b64 [%0], %1;" :: "r"((uint32_t)(a)), "r"((uint32_t)(c)) : "memory")
#define MBAR_WAIT(a, ph) do { \
    uint32_t _m = (uint32_t)(a), _p = (uint32_t)(ph), _d; \
    asm volatile("{\n\t.reg .pred p;\n\tmbarrier.try_wait.parity.acquire.cta.shared::cta.b64 p, [%1], %2;\n\tselp.b32 %0,1,0,p;\n\t}" \
        : "=r"(_d) : "r"(_m), "r"(_p) : "memory"); \
    if (!_d) { asm volatile("{\n\t.reg .pred P1;\n\tWL_%=:\n\t" \
        "mbarrier.try_wait.parity.acquire.cta.shared::cta.b64 P1, [%0], %1, 0x989680;\n\t" \
        "@P1 bra.uni WD_%=;\n\tbra.uni WL_%=;\n\tWD_%=:\n\t}" :: "r"(_m), "r"(_p) : "memory"); } \
} while (0)

#if TC_OK
#define TC_ALLOC(sa, n)   asm volatile("tcgen05.alloc.cta_group::1.sync.aligned.shared::cta.b32 [%0], %1;" :: "r"((uint32_t)(sa)), "r"((uint32_t)(n)) : "memory")
#define TC_DEALLOC(tm, n) asm volatile("tcgen05.dealloc.cta_group::1.sync.aligned.b32 %0, %1;" :: "r"(tm), "r"((uint32_t)(n)))
#define TC_RELINQ()       asm volatile("tcgen05.relinquish_alloc_permit.cta_group::1.sync.aligned;")
#define TC_COMMIT(mb)     asm volatile("tcgen05.commit.cta_group::1.mbarrier::arrive::one.shared::cluster.b64 [%0];" :: "r"((uint32_t)(mb)) : "memory")
#define TC_FENCE_AFTER()  asm volatile("tcgen05.fence::after_thread_sync;" ::: "memory")
#define TC_FENCE_BEFORE() asm volatile("tcgen05.fence::before_thread_sync;" ::: "memory")
#define TC_WAIT_LD()      asm volatile("tcgen05.wait::ld.sync.aligned;" ::: "memory")
#define FENCE_ASYNC()     asm volatile("fence.proxy.async.shared::cta;" ::: "memory")
#define TC_LD_X32(r, ta) \
    asm volatile("tcgen05.ld.sync.aligned.32x32b.x32.b32 " \
        "{%0,%1,%2,%3,%4,%5,%6,%7,%8,%9,%10,%11,%12,%13,%14,%15," \
        "%16,%17,%18,%19,%20,%21,%22,%23,%24,%25,%26,%27,%28,%29,%30,%31}, [%32];" \
        : "=r"((r)[0]), "=r"((r)[1]), "=r"((r)[2]), "=r"((r)[3]), "=r"((r)[4]), "=r"((r)[5]), "=r"((r)[6]), "=r"((r)[7]), \
          "=r"((r)[8]), "=r"((r)[9]), "=r"((r)[10]), "=r"((r)[11]), "=r"((r)[12]), "=r"((r)[13]), "=r"((r)[14]), "=r"((r)[15]), \
          "=r"((r)[16]), "=r"((r)[17]), "=r"((r)[18]), "=r"((r)[19]), "=r"((r)[20]), "=r"((r)[21]), "=r"((r)[22]), "=r"((r)[23]), \
          "=r"((r)[24]), "=r"((r)[25]), "=r"((r)[26]), "=r"((r)[27]), "=r"((r)[28]), "=r"((r)[29]), "=r"((r)[30]), "=r"((r)[31]) \
        : "r"(ta))

// SW64 K-major descriptor: layout=4, version=1, SBO=32 (512B / 8-row group), LBO=1 (16B)
static constexpr uint64_t DESC_SW64 =
    (uint64_t(4) << 61) | (uint64_t(1) << 46) | (uint64_t(32) << 32) | (uint64_t(1) << 16);
#define MK_DESC(a) (DESC_SW64 | ((uint64_t)((a) >> 4) & 0x3FFF))
// idesc kind::f16: F32 out, BF16 a/b, M=128, N=128
#define IDESC ((1u << 4) | (1u << 7) | (1u << 10) | (16u << 17) | (8u << 24))

__device__ __forceinline__ void mma_ss(uint32_t d, uint64_t a, uint64_t b, uint32_t en) {
    asm volatile("{\n\t.reg .pred p;\n\tsetp.ne.u32 p, %4, 0;\n\t"
        "tcgen05.mma.cta_group::1.kind::f16 [%0], %1, %2, %3, {%5,%5,%5,%5}, p;\n\t}"
        :: "r"(d), "l"(a), "l"(b), "r"(IDESC), "r"(en), "r"(0u) : "memory");
}
#endif  // TC_OK

__device__ __forceinline__ uint32_t pack_hi(float a, float b, uint32_t& lo) {
    __nv_bfloat16 h0 = __float2bfloat16(a), h1 = __float2bfloat16(b);
    __nv_bfloat16 l0 = __float2bfloat16(a - __bfloat162float(h0));
    __nv_bfloat16 l1 = __float2bfloat16(b - __bfloat162float(h1));
    lo = (uint32_t)__bfloat16_as_ushort(l0) | ((uint32_t)__bfloat16_as_ushort(l1) << 16);
    return (uint32_t)__bfloat16_as_ushort(h0) | ((uint32_t)__bfloat16_as_ushort(h1) << 16);
}

// ---------------- routing ----------------
__global__ void k_zero() { if (threadIdx.x < E) g_counts[threadIdx.x] = 0; }

__global__ void k_router(const float* __restrict__ x, const float* __restrict__ gate,
                         float* __restrict__ logits_out, int T) {
    __shared__ float sg[E * H];
    for (int i = threadIdx.x; i < E * H; i += blockDim.x) sg[i] = gate[i];
    __syncthreads();
    int warp = threadIdx.x >> 5, lane = threadIdx.x & 31;
    int t = blockIdx.x * 8 + warp;
    if (t >= T) return;
    const float* xr = x + (size_t)t * H;
    float acc[E];
#pragma unroll
    for (int e = 0; e < E; e++) acc[e] = 0.f;
    for (int k = lane; k < H; k += 32) {
        float xv = xr[k];
#pragma unroll
        for (int e = 0; e < E; e++) acc[e] += xv * sg[e * H + k];
    }
#pragma unroll
    for (int e = 0; e < E; e++)
#pragma unroll
        for (int o = 16; o > 0; o >>= 1) acc[e] += __shfl_down_sync(0xffffffffu, acc[e], o);
    if (lane == 0) {
#pragma unroll
        for (int e = 0; e < E; e++) logits_out[(size_t)t * E + e] = acc[e];
        int e0 = 0; float l0 = acc[0];
#pragma unroll
        for (int e = 1; e < E; e++) if (acc[e] > l0) { l0 = acc[e]; e0 = e; }
        int e1 = -1; float l1 = -1e30f;
#pragma unroll
        for (int e = 0; e < E; e++) if (e != e0 && acc[e] > l1) { l1 = acc[e]; e1 = e; }
        float s = 0.f, pe[E];
#pragma unroll
        for (int e = 0; e < E; e++) { pe[e] = expf(acc[e] - l0); s += pe[e]; }
        float p0 = pe[e0] / s, p1 = pe[e1] / s;
        float inv = 1.f / (p0 + p1);
        int q0 = atomicAdd(&g_counts[e0], 1);
        g_list[e0 * T_MAX + q0] = (t << 1);
        g_wts[(t << 1)] = p0 * inv;
        int q1 = atomicAdd(&g_counts[e1], 1);
        g_list[e1 * T_MAX + q1] = (t << 1) | 1;
        g_wts[(t << 1) | 1] = p1 * inv;
    }
}

__global__ void k_base() {
    if (threadIdx.x == 0) {
        int s = 0;
#pragma unroll
        for (int e = 0; e < E; e++) { g_base[e] = s; s += g_counts[e]; }
    }
}

// fp32 -> bf16 hi/lo (8 elems/thread)
__global__ void k_split8(const float* __restrict__ src, __nv_bfloat16* __restrict__ hi,
                         __nv_bfloat16* __restrict__ lo, long n8) {
    long i = (long)blockIdx.x * blockDim.x + threadIdx.x;
    if (i >= n8) return;
    const float4* s4 = (const float4*)src;
    float4 a = s4[2 * i], b = s4[2 * i + 1];
    float v[8] = {a.x, a.y, a.z, a.w, b.x, b.y, b.z, b.w};
    uint32_t ph[4], pl[4];
#pragma unroll
    for (int j = 0; j < 4; j++) ph[j] = pack_hi(v[2 * j], v[2 * j + 1], pl[j]);
    ((uint4*)hi)[i] = make_uint4(ph[0], ph[1], ph[2], ph[3]);
    ((uint4*)lo)[i] = make_uint4(pl[0], pl[1], pl[2], pl[3]);
}

// gather x rows into expert-grouped hi/lo
__global__ void k_gather(const float* __restrict__ x, int total) {
    int g = blockIdx.x;
    if (g >= total) return;
    int e = 0;
#pragma unroll
    for (int k = 1; k < E; k++) if (g >= g_base[k]) e = k;
    int tok = g_list[e * T_MAX + (g - g_base[e])] >> 1;
    const float4* src = (const float4*)(x + (size_t)tok * H);
    uint2* dh = (uint2*)(g_ax_hi + (size_t)g * H);
    uint2* dl = (uint2*)(g_ax_lo + (size_t)g * H);
    for (int i = threadIdx.x; i < H / 4; i += blockDim.x) {
        float4 v = src[i];
        uint32_t l0, l1;
        uint32_t h0 = pack_hi(v.x, v.y, l0);
        uint32_t h1 = pack_hi(v.z, v.w, l1);
        dh[i] = make_uint2(h0, h1);
        dl[i] = make_uint2(l0, l1);
    }
}

// ---------------- SW64 tile loader: 128 rows x 32 bf16 (64B rows) ----------------
// 256 threads, 2 uint4 each.
__device__ __forceinline__ void load_tile64(char* sm, uint32_t off, const __nv_bfloat16* src,
                                            int rbase, int rmax, int K, int k0, int tid) {
#pragma unroll
    for (int j = 0; j < 2; j++) {
        int idx = j * 256 + tid;
        int r = idx >> 2, c = idx & 3;
        int row = rbase + r; if (row > rmax) row = rmax;
        uint4 v = ((const uint4*)(src + (size_t)row * K))[(k0 >> 3) + c];
        *(uint4*)(sm + off + (r << 6) + (((c ^ ((r >> 1) & 3))) << 4)) = v;
    }
}

#define SM_T 1024

// ---------------- tcgen05 GEMM13: BM=256, BN=128 ----------------
// Stage (64KB): Ah0 Al0 Ah1 Al1 W1h W1l W3h W3l (8 x 8KB)
__global__ __launch_bounds__(256, 1) void k_mma13() {
#if TC_OK
    int e = blockIdx.z;
    int cnt = g_counts[e];
    int row0 = blockIdx.y * 256;
    if (row0 >= cnt) return;
    int n0 = blockIdx.x * 128;
    int grow0 = g_base[e] + row0;
    int wrow0 = e * FF + n0;

    extern __shared__ char sm[];
    uint32_t sb = smem_u32(sm);
    int tid = threadIdx.x, wid = tid >> 5, lid = tid & 31;

    if (wid == 0) TC_ALLOC(sb, 512);
    if (tid == 0) { MBAR_INIT(sb + 8, 1); MBAR_INIT(sb + 16, 1); }
    __syncthreads();
    uint32_t tm;
    asm volatile("ld.shared.b32 %0, [%1];" : "=r"(tm) : "r"(sb));

    // chunk 0 -> buf 0
    {
        uint32_t o = SM_T;
        load_tile64(sm, o + 0 * TB, g_ax_hi, grow0,       NROWS - 1, H, 0, tid);
        load_tile64(sm, o + 1 * TB, g_ax_lo, grow0,       NROWS - 1, H, 0, tid);
        load_tile64(sm, o + 2 * TB, g_ax_hi, grow0 + 128, NROWS - 1, H, 0, tid);
        load_tile64(sm, o + 3 * TB, g_ax_lo, grow0 + 128, NROWS - 1, H, 0, tid);
        load_tile64(sm, o + 4 * TB, g_w1h, wrow0, E * FF - 1, H, 0, tid);
        load_tile64(sm, o + 5 * TB, g_w1l, wrow0, E * FF - 1, H, 0, tid);
        load_tile64(sm, o + 6 * TB, g_w3h, wrow0, E * FF - 1, H, 0, tid);
        load_tile64(sm, o + 7 * TB, g_w3l, wrow0, E * FF - 1, H, 0, tid);
    }
    __syncthreads();

    int w0 = 0, w1c = 0;
    const int NCH = H / KC;  // 32
    for (int i = 0; i < NCH; i++) {
        int buf = i & 1;
        if (tid == 0) {
            FENCE_ASYNC();
            TC_FENCE_AFTER();
            uint32_t tb = sb + SM_T + buf * 8 * TB;
            uint64_t dA[4], dW[4];
#pragma unroll
            for (int q = 0; q < 4; q++) { dA[q] = MK_DESC(tb + q * TB); dW[q] = MK_DESC(tb + (4 + q) * TB); }
#pragma unroll
            for (int ks = 0; ks < 2; ks++) {
                uint64_t o = (uint64_t)(2 * ks);
                uint32_t en0 = (i > 0 || ks > 0) ? 1u : 0u;
#pragma unroll
                for (int rh = 0; rh < 2; rh++) {
                    uint32_t a1 = tm + rh * 256, a3 = tm + rh * 256 + 128;
                    uint64_t ah = dA[rh * 2], al = dA[rh * 2 + 1];
                    mma_ss(a1, ah + o, dW[0] + o, en0);
                    mma_ss(a1, ah + o, dW[1] + o, 1);
                    mma_ss(a1, al + o, dW[0] + o, 1);
                    mma_ss(a3, ah + o, dW[2] + o, en0);
                    mma_ss(a3, ah + o, dW[3] + o, 1);
                    mma_ss(a3, al + o, dW[2] + o, 1);
                }
            }
            TC_COMMIT(sb + 8 + buf * 8);
        }
        if (i + 1 < NCH) {
            int nb = (i + 1) & 1;
            if (i >= 1) {
                if (nb == 0) { MBAR_WAIT(sb + 8, w0 & 1); w0++; }
                else         { MBAR_WAIT(sb + 16, w1c & 1); w1c++; }
            }
            int k0 = (i + 1) * KC;
            uint32_t o = SM_T + nb * 8 * TB;
            load_tile64(sm, o + 0 * TB, g_ax_hi, grow0,       NROWS - 1, H, k0, tid);
            load_tile64(sm, o + 1 * TB, g_ax_lo, grow0,       NROWS - 1, H, k0, tid);
            load_tile64(sm, o + 2 * TB, g_ax_hi, grow0 + 128, NROWS - 1, H, k0, tid);
            load_tile64(sm, o + 3 * TB, g_ax_lo, grow0 + 128, NROWS - 1, H, k0, tid);
            load_tile64(sm, o + 4 * TB, g_w1h, wrow0, E * FF - 1, H, k0, tid);
            load_tile64(sm, o + 5 * TB, g_w1l, wrow0, E * FF - 1, H, k0, tid);
            load_tile64(sm, o + 6 * TB, g_w3h, wrow0, E * FF - 1, H, k0, tid);
            load_tile64(sm, o + 7 * TB, g_w3l, wrow0, E * FF - 1, H, k0, tid);
            __syncthreads();
        }
    }
    MBAR_WAIT(sb + 8, w0 & 1);
    MBAR_WAIT(sb + 16, w1c & 1);
    TC_FENCE_AFTER();

    // epilogue: 8 warps = 2 rowhalves x 4 subpartitions
    int rh = wid >> 2, sub = wid & 3;
    int rloc = rh * 128 + sub * 32 + lid;
    bool valid = (row0 + rloc) < cnt;
    size_t arow = (size_t)(grow0 + rloc) * FF + n0;
#pragma unroll
    for (int c0 = 0; c0 < 128; c0 += 32) {
        uint32_t d1[32], d3[32];
        TC_LD_X32(d1, tm + rh * 256 + c0);
        TC_LD_X32(d3, tm + rh * 256 + 128 + c0);
        TC_WAIT_LD();
        if (valid) {
            uint32_t ph[16], pl[16];
#pragma unroll
            for (int j = 0; j < 16; j++) {
                float h0 = __uint_as_float(d1[2 * j]),     v0 = __uint_as_float(d3[2 * j]);
                float h1 = __uint_as_float(d1[2 * j + 1]), v1 = __uint_as_float(d3[2 * j + 1]);
                float a0 = (h0 / (1.f + __expf(-h0))) * v0;
                float a1 = (h1 / (1.f + __expf(-h1))) * v1;
                ph[j] = pack_hi(a0, a1, pl[j]);
            }
            uint4* dh = (uint4*)(g_act_hi + arow + c0);
            uint4* dl = (uint4*)(g_act_lo + arow + c0);
#pragma unroll
            for (int q = 0; q < 4; q++) {
                dh[q] = make_uint4(ph[4 * q], ph[4 * q + 1], ph[4 * q + 2], ph[4 * q + 3]);
                dl[q] = make_uint4(pl[4 * q], pl[4 * q + 1], pl[4 * q + 2], pl[4 * q + 3]);
            }
        }
    }
    TC_FENCE_BEFORE();
    __syncthreads();
    if (wid == 0) { TC_RELINQ(); TC_DEALLOC(tm, 512); }
#endif
}

// ---------------- tcgen05 GEMM2: BM=256, BN=128 ----------------
// Stage (48KB): Ah0 Al0 Ah1 Al1 W2h W2l (6 x 8KB)
__global__ __launch_bounds__(256, 1) void k_mma2() {
#if TC_OK
    int e = blockIdx.z;
    int cnt = g_counts[e];
    int row0 = blockIdx.y * 256;
    if (row0 >= cnt) return;
    int n0 = blockIdx.x * 128;
    int grow0 = g_base[e] + row0;
    int wrow0 = e * H + n0;

    extern __shared__ char sm[];
    uint32_t sb = smem_u32(sm);
    int tid = threadIdx.x, wid = tid >> 5, lid = tid & 31;

    if (wid == 0) TC_ALLOC(sb, 256);
    if (tid == 0) { MBAR_INIT(sb + 8, 1); MBAR_INIT(sb + 16, 1); }
    __syncthreads();
    uint32_t tm;
    asm volatile("ld.shared.b32 %0, [%1];" : "=r"(tm) : "r"(sb));

    {
        uint32_t o = SM_T;
        load_tile64(sm, o + 0 * TB, g_act_hi, grow0,       NROWS - 1, FF, 0, tid);
        load_tile64(sm, o + 1 * TB, g_act_lo, grow0,       NROWS - 1, FF, 0, tid);
        load_tile64(sm, o + 2 * TB, g_act_hi, grow0 + 128, NROWS - 1, FF, 0, tid);
        load_tile64(sm, o + 3 * TB, g_act_lo, grow0 + 128, NROWS - 1, FF, 0, tid);
        load_tile64(sm, o + 4 * TB, g_w2h, wrow0, E * H - 1, FF, 0, tid);
        load_tile64(sm, o + 5 * TB, g_w2l, wrow0, E * H - 1, FF, 0, tid);
    }
    __syncthreads();

    int w0 = 0, w1c = 0;
    const int NCH = FF / KC;  // 128
    for (int i = 0; i < NCH; i++) {
        int buf = i & 1;
        if (tid == 0) {
            FENCE_ASYNC();
            TC_FENCE_AFTER();
            uint32_t tb = sb + SM_T + buf * 6 * TB;
            uint64_t dA[4];
#pragma unroll
            for (int q = 0; q < 4; q++) dA[q] = MK_DESC(tb + q * TB);
            uint64_t dWh = MK_DESC(tb + 4 * TB), dWl = MK_DESC(tb + 5 * TB);
#pragma unroll
            for (int ks = 0; ks < 2; ks++) {
                uint64_t o = (uint64_t)(2 * ks);
                uint32_t en0 = (i > 0 || ks > 0) ? 1u : 0u;
#pragma unroll
                for (int rh = 0; rh < 2; rh++) {
                    uint32_t acc = tm + rh * 128;
                    uint64_t ah = dA[rh * 2], al = dA[rh * 2 + 1];
                    mma_ss(acc, ah + o, dWh + o, en0);
                    mma_ss(acc, ah + o, dWl + o, 1);
                    mma_ss(acc, al + o, dWh + o, 1);
                }
            }
            TC_COMMIT(sb + 8 + buf * 8);
        }
        if (i + 1 < NCH) {
            int nb = (i + 1) & 1;
            if (i >= 1) {
                if (nb == 0) { MBAR_WAIT(sb + 8, w0 & 1); w0++; }
                else         { MBAR_WAIT(sb + 16, w1c & 1); w1c++; }
            }
            int k0 = (i + 1) * KC;
            uint32_t o = SM_T + nb * 6 * TB;
            load_tile64(sm, o + 0 * TB, g_act_hi, grow0,       NROWS - 1, FF, k0, tid);
            load_tile64(sm, o + 1 * TB, g_act_lo, grow0,       NROWS - 1, FF, k0, tid);
            load_tile64(sm, o + 2 * TB, g_act_hi, grow0 + 128, NROWS - 1, FF, k0, tid);
            load_tile64(sm, o + 3 * TB, g_act_lo, grow0 + 128, NROWS - 1, FF, k0, tid);
            load_tile64(sm, o + 4 * TB, g_w2h, wrow0, E * H - 1, FF, k0, tid);
            load_tile64(sm, o + 5 * TB, g_w2l, wrow0, E * H - 1, FF, k0, tid);
            __syncthreads();
        }
    }
    MBAR_WAIT(sb + 8, w0 & 1);
    MBAR_WAIT(sb + 16, w1c & 1);
    TC_FENCE_AFTER();

    int rh = wid >> 2, sub = wid & 3;
    int rloc = rh * 128 + sub * 32 + lid;
    bool valid = (row0 + rloc) < cnt;
    int ts = 0; float w = 0.f;
    if (valid) { ts = g_list[e * T_MAX + row0 + rloc]; w = g_wts[ts]; }
    float* yrow = g_ybuf + (size_t)ts * H + n0;
#pragma unroll
    for (int c0 = 0; c0 < 128; c0 += 32) {
        uint32_t d[32];
        TC_LD_X32(d, tm + rh * 128 + c0);
        TC_WAIT_LD();
        if (valid) {
            float4* dst = (float4*)(yrow + c0);
#pragma unroll
            for (int q = 0; q < 8; q++)
                dst[q] = make_float4(w * __uint_as_float(d[4 * q]), w * __uint_as_float(d[4 * q + 1]),
                                     w * __uint_as_float(d[4 * q + 2]), w * __uint_as_float(d[4 * q + 3]));
        }
    }
    TC_FENCE_BEFORE();
    __syncthreads();
    if (wid == 0) { TC_RELINQ(); TC_DEALLOC(tm, 256); }
#endif
}

__global__ void k_combine(float* __restrict__ out, int T) {
    int i = blockIdx.x * blockDim.x + threadIdx.x;
    int total = T * (H / 4);
    if (i >= total) return;
    int t = i / (H / 4);
    int h4 = i - t * (H / 4);
    const float4* yb = (const float4*)g_ybuf;
    float4 a = yb[(size_t)(2 * t) * (H / 4) + h4];
    float4 b = yb[(size_t)(2 * t + 1) * (H / 4) + h4];
    ((float4*)out)[i] = make_float4(a.x + b.x, a.y + b.y, a.z + b.z, a.w + b.w);
}

// ---------------- launch ----------------
extern "C" void kernel_launch(void* const* d_in, const int* in_sizes, int n_in,
                              void* d_out, int out_size) {
    const float* x;
    const float* gate;
    if (in_sizes[0] > in_sizes[1]) { x = (const float*)d_in[0]; gate = (const float*)d_in[1]; }
    else                           { gate = (const float*)d_in[0]; x = (const float*)d_in[1]; }
    const float* w1 = (const float*)d_in[2];
    const float* w2 = (const float*)d_in[3];
    const float* w3 = (const float*)d_in[4];
    int T = (in_sizes[0] > in_sizes[1] ? in_sizes[0] : in_sizes[1]) / H;

    float* out = (float*)d_out;
    float* logits_out = out + (size_t)T * H;

    int smem13 = SM_T + 2 * 8 * TB;  // 132,096
    int smem2  = SM_T + 2 * 6 * TB;  //  99,328
    cudaFuncSetAttribute(k_mma13, cudaFuncAttributeMaxDynamicSharedMemorySize, smem13);
    cudaFuncSetAttribute(k_mma2,  cudaFuncAttributeMaxDynamicSharedMemorySize, smem2);

    __nv_bfloat16 *w1h, *w1l, *w3h, *w3l, *w2h, *w2l;
    cudaGetSymbolAddress((void**)&w1h, g_w1h); cudaGetSymbolAddress((void**)&w1l, g_w1l);
    cudaGetSymbolAddress((void**)&w3h, g_w3h); cudaGetSymbolAddress((void**)&w3l, g_w3l);
    cudaGetSymbolAddress((void**)&w2h, g_w2h); cudaGetSymbolAddress((void**)&w2l, g_w2l);

    k_zero<<<1, 32>>>();
    k_router<<<(T + 7) / 8, 256>>>(x, gate, logits_out, T);
    k_base<<<1, 1>>>();

    long n8 = (long)E * FF * H / 8;
    int sblk = (int)((n8 + 255) / 256);
    k_split8<<<sblk, 256>>>(w1, w1h, w1l, n8);
    k_split8<<<sblk, 256>>>(w3, w3h, w3l, n8);
    k_split8<<<sblk, 256>>>(w2, w2h, w2l, n8);
    k_gather<<<2 * T, 128>>>(x, 2 * T);

    int ytiles = (2 * T + 255) / 256;  // per-expert upper bound via early exit
    dim3 g13(FF / 128, ytiles, E);
    k_mma13<<<g13, 256, smem13>>>();
    dim3 g2(H / 128, ytiles, E);
    k_mma2<<<g2, 256, smem2>>>();

    k_combine<<<(T * (H / 4) + 255) / 256, 256>>>(out, T);
}

// round 7
// speedup vs baseline: 11.6827x; 1.2537x over previous
#include <cuda_runtime.h>
#include <cuda_bf16.h>
#include <cstdint>
#include <stdint.h>
#include <math.h>

#define H     1024
#define FF    4096
#define E     8
#define T_MAX 8192
#define NROWS (T_MAX * 2)
#define KC    32          // K-chunk
#define TB    8192        // 128 rows x 64 bytes (SW64 tile)

#if defined(__CUDA_ARCH_FEAT_SM103_ALL) || defined(__CUDA_ARCH_FEAT_SM100_ALL)
#define TC_OK 1
#else
#define TC_OK 0
#endif

// ---------------- device scratch ----------------
__device__ int   g_counts[E];
__device__ int   g_base[E];
__device__ int   g_list[E * T_MAX];
__device__ float g_wts[T_MAX * 2];
__device__ __nv_bfloat16 g_ax_hi[(size_t)NROWS * H];
__device__ __nv_bfloat16 g_ax_lo[(size_t)NROWS * H];
__device__ __nv_bfloat16 g_w1h[(size_t)E * FF * H];
__device__ __nv_bfloat16 g_w1l[(size_t)E * FF * H];
__device__ __nv_bfloat16 g_w3h[(size_t)E * FF * H];
__device__ __nv_bfloat16 g_w3l[(size_t)E * FF * H];
__device__ __nv_bfloat16 g_w2h[(size_t)E * H * FF];
__device__ __nv_bfloat16 g_w2l[(size_t)E * H * FF];
__device__ __nv_bfloat16 g_act_hi[(size_t)NROWS * FF];
__device__ __nv_bfloat16 g_act_lo[(size_t)NROWS * FF];
__device__ float g_ybuf[(size_t)NROWS * H];

// ---------------- PTX helpers ----------------
__device__ __forceinline__ uint32_t smem_u32(const void* p) {
    uint32_t a;
    asm("{ .reg .u64 t; cvta.to.shared.u64 t, %1; cvt.u32.u64 %0, t; }" : "=r"(a) : "l"(p));
    return a;
}
#define MBAR_INIT(a, c) asm volatile("mbarrier.init.shared.b64 [%0], %1;" :: "r"((uint32_t)(a)), "r"((uint32_t)(c)) : "memory")
#define MBAR_WAIT(a, ph) do { \
    uint32_t _m = (uint32_t)(a), _p = (uint32_t)(ph), _d; \
    asm volatile("{\n\t.reg .pred p;\n\tmbarrier.try_wait.parity.acquire.cta.shared::cta.b64 p, [%1], %2;\n\tselp.b32 %0,1,0,p;\n\t}" \
        : "=r"(_d) : "r"(_m), "r"(_p) : "memory"); \
    if (!_d) { asm volatile("{\n\t.reg .pred P1;\n\tWL_%=:\n\t" \
        "mbarrier.try_wait.parity.acquire.cta.shared::cta.b64 P1, [%0], %1, 0x989680;\n\t" \
        "@P1 bra.uni WD_%=;\n\tbra.uni WL_%=;\n\tWD_%=:\n\t}" :: "r"(_m), "r"(_p) : "memory"); } \
} while (0)

#define CP16(d, s)  asm volatile("cp.async.cg.shared.global [%0], [%1], 16;" :: "r"((uint32_t)(d)), "l"(s) : "memory")
#define CP_COMMIT() asm volatile("cp.async.commit_group;" ::: "memory")
#define CP_WAIT0()  asm volatile("cp.async.wait_group 0;" ::: "memory")

#if TC_OK
#define TC_ALLOC(sa, n)   asm volatile("tcgen05.alloc.cta_group::1.sync.aligned.shared::cta.b32 [%0], %1;" :: "r"((uint32_t)(sa)), "r"((uint32_t)(n)) : "memory")
#define TC_DEALLOC(tm, n) asm volatile("tcgen05.dealloc.cta_group::1.sync.aligned.b32 %0, %1;" :: "r"(tm), "r"((uint32_t)(n)))
#define TC_RELINQ()       asm volatile("tcgen05.relinquish_alloc_permit.cta_group::1.sync.aligned;")
#define TC_COMMIT(mb)     asm volatile("tcgen05.commit.cta_group::1.mbarrier::arrive::one.shared::cluster.b64 [%0];" :: "r"((uint32_t)(mb)) : "memory")
#define TC_FENCE_AFTER()  asm volatile("tcgen05.fence::after_thread_sync;" ::: "memory")
#define TC_FENCE_BEFORE() asm volatile("tcgen05.fence::before_thread_sync;" ::: "memory")
#define TC_WAIT_LD()      asm volatile("tcgen05.wait::ld.sync.aligned;" ::: "memory")
#define FENCE_ASYNC()     asm volatile("fence.proxy.async.shared::cta;" ::: "memory")
#define TC_LD_X32(r, ta) \
    asm volatile("tcgen05.ld.sync.aligned.32x32b.x32.b32 " \
        "{%0,%1,%2,%3,%4,%5,%6,%7,%8,%9,%10,%11,%12,%13,%14,%15," \
        "%16,%17,%18,%19,%20,%21,%22,%23,%24,%25,%26,%27,%28,%29,%30,%31}, [%32];" \
        : "=r"((r)[0]), "=r"((r)[1]), "=r"((r)[2]), "=r"((r)[3]), "=r"((r)[4]), "=r"((r)[5]), "=r"((r)[6]), "=r"((r)[7]), \
          "=r"((r)[8]), "=r"((r)[9]), "=r"((r)[10]), "=r"((r)[11]), "=r"((r)[12]), "=r"((r)[13]), "=r"((r)[14]), "=r"((r)[15]), \
          "=r"((r)[16]), "=r"((r)[17]), "=r"((r)[18]), "=r"((r)[19]), "=r"((r)[20]), "=r"((r)[21]), "=r"((r)[22]), "=r"((r)[23]), \
          "=r"((r)[24]), "=r"((r)[25]), "=r"((r)[26]), "=r"((r)[27]), "=r"((r)[28]), "=r"((r)[29]), "=r"((r)[30]), "=r"((r)[31]) \
        : "r"(ta))

// SW64 K-major descriptor: layout=4, version=1, SBO=32 (512B per 8-row group), LBO=1
static constexpr uint64_t DESC_SW64 =
    (uint64_t(4) << 61) | (uint64_t(1) << 46) | (uint64_t(32) << 32) | (uint64_t(1) << 16);
#define MK_DESC(a) (DESC_SW64 | ((uint64_t)((a) >> 4) & 0x3FFF))
// idesc kind::f16: F32 out, BF16 a/b, M=128, N=256 (B spans two adjacent 128-row tiles)
#define IDESC256 ((1u << 4) | (1u << 7) | (1u << 10) | (32u << 17) | (8u << 24))

__device__ __forceinline__ void mma256(uint32_t d, uint64_t a, uint64_t b, uint32_t en) {
    asm volatile("{\n\t.reg .pred p;\n\tsetp.ne.u32 p, %4, 0;\n\t"
        "tcgen05.mma.cta_group::1.kind::f16 [%0], %1, %2, %3, {%5,%5,%5,%5}, p;\n\t}"
        :: "r"(d), "l"(a), "l"(b), "r"(IDESC256), "r"(en), "r"(0u) : "memory");
}
#endif  // TC_OK

__device__ __forceinline__ uint32_t pack_hi(float a, float b, uint32_t& lo) {
    __nv_bfloat16 h0 = __float2bfloat16(a), h1 = __float2bfloat16(b);
    __nv_bfloat16 l0 = __float2bfloat16(a - __bfloat162float(h0));
    __nv_bfloat16 l1 = __float2bfloat16(b - __bfloat162float(h1));
    lo = (uint32_t)__bfloat16_as_ushort(l0) | ((uint32_t)__bfloat16_as_ushort(l1) << 16);
    return (uint32_t)__bfloat16_as_ushort(h0) | ((uint32_t)__bfloat16_as_ushort(h1) << 16);
}

// ---------------- routing ----------------
__global__ void k_zero() { if (threadIdx.x < E) g_counts[threadIdx.x] = 0; }

__global__ void k_router(const float* __restrict__ x, const float* __restrict__ gate,
                         float* __restrict__ logits_out, int T) {
    __shared__ float sg[E * H];
    for (int i = threadIdx.x; i < E * H; i += blockDim.x) sg[i] = gate[i];
    __syncthreads();
    int warp = threadIdx.x >> 5, lane = threadIdx.x & 31;
    int t = blockIdx.x * 8 + warp;
    if (t >= T) return;
    const float* xr = x + (size_t)t * H;
    float acc[E];
#pragma unroll
    for (int e = 0; e < E; e++) acc[e] = 0.f;
    for (int k = lane; k < H; k += 32) {
        float xv = xr[k];
#pragma unroll
        for (int e = 0; e < E; e++) acc[e] += xv * sg[e * H + k];
    }
#pragma unroll
    for (int e = 0; e < E; e++)
#pragma unroll
        for (int o = 16; o > 0; o >>= 1) acc[e] += __shfl_down_sync(0xffffffffu, acc[e], o);
    if (lane == 0) {
#pragma unroll
        for (int e = 0; e < E; e++) logits_out[(size_t)t * E + e] = acc[e];
        int e0 = 0; float l0 = acc[0];
#pragma unroll
        for (int e = 1; e < E; e++) if (acc[e] > l0) { l0 = acc[e]; e0 = e; }
        int e1 = -1; float l1 = -1e30f;
#pragma unroll
        for (int e = 0; e < E; e++) if (e != e0 && acc[e] > l1) { l1 = acc[e]; e1 = e; }
        float s = 0.f, pe[E];
#pragma unroll
        for (int e = 0; e < E; e++) { pe[e] = expf(acc[e] - l0); s += pe[e]; }
        float p0 = pe[e0] / s, p1 = pe[e1] / s;
        float inv = 1.f / (p0 + p1);
        int q0 = atomicAdd(&g_counts[e0], 1);
        g_list[e0 * T_MAX + q0] = (t << 1);
        g_wts[(t << 1)] = p0 * inv;
        int q1 = atomicAdd(&g_counts[e1], 1);
        g_list[e1 * T_MAX + q1] = (t << 1) | 1;
        g_wts[(t << 1) | 1] = p1 * inv;
    }
}

__global__ void k_base() {
    if (threadIdx.x == 0) {
        int s = 0;
#pragma unroll
        for (int e = 0; e < E; e++) { g_base[e] = s; s += g_counts[e]; }
    }
}

// fp32 -> bf16 hi/lo (8 elems/thread)
__global__ void k_split8(const float* __restrict__ src, __nv_bfloat16* __restrict__ hi,
                         __nv_bfloat16* __restrict__ lo, long n8) {
    long i = (long)blockIdx.x * blockDim.x + threadIdx.x;
    if (i >= n8) return;
    const float4* s4 = (const float4*)src;
    float4 a = s4[2 * i], b = s4[2 * i + 1];
    float v[8] = {a.x, a.y, a.z, a.w, b.x, b.y, b.z, b.w};
    uint32_t ph[4], pl[4];
#pragma unroll
    for (int j = 0; j < 4; j++) ph[j] = pack_hi(v[2 * j], v[2 * j + 1], pl[j]);
    ((uint4*)hi)[i] = make_uint4(ph[0], ph[1], ph[2], ph[3]);
    ((uint4*)lo)[i] = make_uint4(pl[0], pl[1], pl[2], pl[3]);
}

// gather x rows into expert-grouped hi/lo
__global__ void k_gather(const float* __restrict__ x, int total) {
    int g = blockIdx.x;
    if (g >= total) return;
    int e = 0;
#pragma unroll
    for (int k = 1; k < E; k++) if (g >= g_base[k]) e = k;
    int tok = g_list[e * T_MAX + (g - g_base[e])] >> 1;
    const float4* src = (const float4*)(x + (size_t)tok * H);
    uint2* dh = (uint2*)(g_ax_hi + (size_t)g * H);
    uint2* dl = (uint2*)(g_ax_lo + (size_t)g * H);
    for (int i = threadIdx.x; i < H / 4; i += blockDim.x) {
        float4 v = src[i];
        uint32_t l0, l1;
        uint32_t h0 = pack_hi(v.x, v.y, l0);
        uint32_t h1 = pack_hi(v.z, v.w, l1);
        dh[i] = make_uint2(h0, h1);
        dl[i] = make_uint2(l0, l1);
    }
}

// ---------------- SW64 cp.async tile loader: 128 rows x 32 bf16 ----------------
__device__ __forceinline__ void cp_tile64(uint32_t dst, const __nv_bfloat16* src,
                                          int rbase, int rmax, int K, int k0, int tid) {
#pragma unroll
    for (int j = 0; j < 2; j++) {
        int idx = j * 256 + tid;
        int r = idx >> 2, c = idx & 3;
        int row = rbase + r; if (row > rmax) row = rmax;
        const char* s = (const char*)(src + (size_t)row * K) + k0 * 2 + c * 16;
        CP16(dst + (r << 6) + ((c ^ ((r >> 1) & 3)) << 4), s);
    }
}

#define SM_T 1024

// ---------------- tcgen05 GEMM13: BM=256, BN=128, 3-stage, N=256 MMA ----------------
// Stage (64KB): Ah0 Al0 Ah1 Al1 | W1h W3h | W1l W3l
__global__ __launch_bounds__(256, 1) void k_mma13() {
#if TC_OK
    int e = blockIdx.z;
    int cnt = g_counts[e];
    int row0 = blockIdx.y * 256;
    if (row0 >= cnt) return;
    int n0 = blockIdx.x * 128;
    int grow0 = g_base[e] + row0;
    int wrow0 = e * FF + n0;

    extern __shared__ char sm[];
    uint32_t sb = smem_u32(sm);
    int tid = threadIdx.x, wid = tid >> 5, lid = tid & 31;

    if (wid == 0) TC_ALLOC(sb, 512);
    if (tid == 0) { MBAR_INIT(sb + 8, 1); MBAR_INIT(sb + 16, 1); MBAR_INIT(sb + 24, 1); }
    __syncthreads();
    uint32_t tm;
    asm volatile("ld.shared.b32 %0, [%1];" : "=r"(tm) : "r"(sb));

    const int NCH = H / KC;  // 32
    // prologue: chunks 0,1 -> bufs 0,1
#pragma unroll
    for (int p = 0; p < 2; p++) {
        uint32_t o = sb + SM_T + p * 8 * TB;
        int k0 = p * KC;
        cp_tile64(o + 0 * TB, g_ax_hi, grow0,       NROWS - 1, H, k0, tid);
        cp_tile64(o + 1 * TB, g_ax_lo, grow0,       NROWS - 1, H, k0, tid);
        cp_tile64(o + 2 * TB, g_ax_hi, grow0 + 128, NROWS - 1, H, k0, tid);
        cp_tile64(o + 3 * TB, g_ax_lo, grow0 + 128, NROWS - 1, H, k0, tid);
        cp_tile64(o + 4 * TB, g_w1h, wrow0, E * FF - 1, H, k0, tid);
        cp_tile64(o + 5 * TB, g_w3h, wrow0, E * FF - 1, H, k0, tid);
        cp_tile64(o + 6 * TB, g_w1l, wrow0, E * FF - 1, H, k0, tid);
        cp_tile64(o + 7 * TB, g_w3l, wrow0, E * FF - 1, H, k0, tid);
        CP_COMMIT();
    }
    CP_WAIT0();
    __syncthreads();

    int wc[3] = {0, 0, 0};
    for (int i = 0; i < NCH; i++) {
        int buf = i % 3;
        if (tid == 0) {
            FENCE_ASYNC();
            TC_FENCE_AFTER();
            uint32_t tb = sb + SM_T + buf * 8 * TB;
            uint64_t dAh0 = MK_DESC(tb),          dAl0 = MK_DESC(tb + TB);
            uint64_t dAh1 = MK_DESC(tb + 2 * TB), dAl1 = MK_DESC(tb + 3 * TB);
            uint64_t dWh  = MK_DESC(tb + 4 * TB), dWl  = MK_DESC(tb + 6 * TB);
#pragma unroll
            for (int ks = 0; ks < 2; ks++) {
                uint64_t o = (uint64_t)(2 * ks);
                uint32_t en = (i > 0 || ks > 0) ? 1u : 0u;
                mma256(tm,       dAh0 + o, dWh + o, en);
                mma256(tm,       dAh0 + o, dWl + o, 1);
                mma256(tm,       dAl0 + o, dWh + o, 1);
                mma256(tm + 256, dAh1 + o, dWh + o, en);
                mma256(tm + 256, dAh1 + o, dWl + o, 1);
                mma256(tm + 256, dAl1 + o, dWh + o, 1);
            }
            TC_COMMIT(sb + 8 + buf * 8);
        }
        if (i + 2 < NCH) {
            int pb = (i - 1 + 3) % 3;  // == (i+2)%3
            if (i >= 1) { MBAR_WAIT(sb + 8 + pb * 8, wc[pb] & 1); wc[pb]++; }
            int k0 = (i + 2) * KC;
            uint32_t o = sb + SM_T + ((i + 2) % 3) * 8 * TB;
            cp_tile64(o + 0 * TB, g_ax_hi, grow0,       NROWS - 1, H, k0, tid);
            cp_tile64(o + 1 * TB, g_ax_lo, grow0,       NROWS - 1, H, k0, tid);
            cp_tile64(o + 2 * TB, g_ax_hi, grow0 + 128, NROWS - 1, H, k0, tid);
            cp_tile64(o + 3 * TB, g_ax_lo, grow0 + 128, NROWS - 1, H, k0, tid);
            cp_tile64(o + 4 * TB, g_w1h, wrow0, E * FF - 1, H, k0, tid);
            cp_tile64(o + 5 * TB, g_w3h, wrow0, E * FF - 1, H, k0, tid);
            cp_tile64(o + 6 * TB, g_w1l, wrow0, E * FF - 1, H, k0, tid);
            cp_tile64(o + 7 * TB, g_w3l, wrow0, E * FF - 1, H, k0, tid);
            CP_COMMIT();
            CP_WAIT0();
            __syncthreads();
        }
    }
    // final waits: last commit parity per buffer
#pragma unroll
    for (int b = 0; b < 3; b++) {
        int tot = (NCH - b + 2) / 3;
        if (tot > 0) MBAR_WAIT(sb + 8 + b * 8, (tot - 1) & 1);
    }
    TC_FENCE_AFTER();

    int rh = wid >> 2, sub = wid & 3;
    int rloc = rh * 128 + sub * 32 + lid;
    bool valid = (row0 + rloc) < cnt;
    size_t arow = (size_t)(grow0 + rloc) * FF + n0;
#pragma unroll
    for (int c0 = 0; c0 < 128; c0 += 32) {
        uint32_t d1[32], d3[32];
        TC_LD_X32(d1, tm + rh * 256 + c0);
        TC_LD_X32(d3, tm + rh * 256 + 128 + c0);
        TC_WAIT_LD();
        if (valid) {
            uint32_t ph[16], pl[16];
#pragma unroll
            for (int j = 0; j < 16; j++) {
                float h0 = __uint_as_float(d1[2 * j]),     v0 = __uint_as_float(d3[2 * j]);
                float h1 = __uint_as_float(d1[2 * j + 1]), v1 = __uint_as_float(d3[2 * j + 1]);
                float a0 = (h0 / (1.f + __expf(-h0))) * v0;
                float a1 = (h1 / (1.f + __expf(-h1))) * v1;
                ph[j] = pack_hi(a0, a1, pl[j]);
            }
            uint4* dh = (uint4*)(g_act_hi + arow + c0);
            uint4* dl = (uint4*)(g_act_lo + arow + c0);
#pragma unroll
            for (int q = 0; q < 4; q++) {
                dh[q] = make_uint4(ph[4 * q], ph[4 * q + 1], ph[4 * q + 2], ph[4 * q + 3]);
                dl[q] = make_uint4(pl[4 * q], pl[4 * q + 1], pl[4 * q + 2], pl[4 * q + 3]);
            }
        }
    }
    TC_FENCE_BEFORE();
    __syncthreads();
    if (wid == 0) { TC_RELINQ(); TC_DEALLOC(tm, 512); }
#endif
}

// ---------------- tcgen05 GEMM2: BM=256, BN=256, 3-stage, N=256 MMA ----------------
// Stage (64KB): Ah0 Al0 Ah1 Al1 | W2h_a W2h_b | W2l_a W2l_b
__global__ __launch_bounds__(256, 1) void k_mma2() {
#if TC_OK
    int e = blockIdx.z;
    int cnt = g_counts[e];
    int row0 = blockIdx.y * 256;
    if (row0 >= cnt) return;
    int n0 = blockIdx.x * 256;
    int grow0 = g_base[e] + row0;
    int wrow0 = e * H + n0;

    extern __shared__ char sm[];
    uint32_t sb = smem_u32(sm);
    int tid = threadIdx.x, wid = tid >> 5, lid = tid & 31;

    if (wid == 0) TC_ALLOC(sb, 512);
    if (tid == 0) { MBAR_INIT(sb + 8, 1); MBAR_INIT(sb + 16, 1); MBAR_INIT(sb + 24, 1); }
    __syncthreads();
    uint32_t tm;
    asm volatile("ld.shared.b32 %0, [%1];" : "=r"(tm) : "r"(sb));

    const int NCH = FF / KC;  // 128
#pragma unroll
    for (int p = 0; p < 2; p++) {
        uint32_t o = sb + SM_T + p * 8 * TB;
        int k0 = p * KC;
        cp_tile64(o + 0 * TB, g_act_hi, grow0,       NROWS - 1, FF, k0, tid);
        cp_tile64(o + 1 * TB, g_act_lo, grow0,       NROWS - 1, FF, k0, tid);
        cp_tile64(o + 2 * TB, g_act_hi, grow0 + 128, NROWS - 1, FF, k0, tid);
        cp_tile64(o + 3 * TB, g_act_lo, grow0 + 128, NROWS - 1, FF, k0, tid);
        cp_tile64(o + 4 * TB, g_w2h, wrow0,       E * H - 1, FF, k0, tid);
        cp_tile64(o + 5 * TB, g_w2h, wrow0 + 128, E * H - 1, FF, k0, tid);
        cp_tile64(o + 6 * TB, g_w2l, wrow0,       E * H - 1, FF, k0, tid);
        cp_tile64(o + 7 * TB, g_w2l, wrow0 + 128, E * H - 1, FF, k0, tid);
        CP_COMMIT();
    }
    CP_WAIT0();
    __syncthreads();

    int wc[3] = {0, 0, 0};
    for (int i = 0; i < NCH; i++) {
        int buf = i % 3;
        if (tid == 0) {
            FENCE_ASYNC();
            TC_FENCE_AFTER();
            uint32_t tb = sb + SM_T + buf * 8 * TB;
            uint64_t dAh0 = MK_DESC(tb),          dAl0 = MK_DESC(tb + TB);
            uint64_t dAh1 = MK_DESC(tb + 2 * TB), dAl1 = MK_DESC(tb + 3 * TB);
            uint64_t dWh  = MK_DESC(tb + 4 * TB), dWl  = MK_DESC(tb + 6 * TB);
#pragma unroll
            for (int ks = 0; ks < 2; ks++) {
                uint64_t o = (uint64_t)(2 * ks);
                uint32_t en = (i > 0 || ks > 0) ? 1u : 0u;
                mma256(tm,       dAh0 + o, dWh + o, en);
                mma256(tm,       dAh0 + o, dWl + o, 1);
                mma256(tm,       dAl0 + o, dWh + o, 1);
                mma256(tm + 256, dAh1 + o, dWh + o, en);
                mma256(tm + 256, dAh1 + o, dWl + o, 1);
                mma256(tm + 256, dAl1 + o, dWh + o, 1);
            }
            TC_COMMIT(sb + 8 + buf * 8);
        }
        if (i + 2 < NCH) {
            int pb = (i - 1 + 3) % 3;
            if (i >= 1) { MBAR_WAIT(sb + 8 + pb * 8, wc[pb] & 1); wc[pb]++; }
            int k0 = (i + 2) * KC;
            uint32_t o = sb + SM_T + ((i + 2) % 3) * 8 * TB;
            cp_tile64(o + 0 * TB, g_act_hi, grow0,       NROWS - 1, FF, k0, tid);
            cp_tile64(o + 1 * TB, g_act_lo, grow0,       NROWS - 1, FF, k0, tid);
            cp_tile64(o + 2 * TB, g_act_hi, grow0 + 128, NROWS - 1, FF, k0, tid);
            cp_tile64(o + 3 * TB, g_act_lo, grow0 + 128, NROWS - 1, FF, k0, tid);
            cp_tile64(o + 4 * TB, g_w2h, wrow0,       E * H - 1, FF, k0, tid);
            cp_tile64(o + 5 * TB, g_w2h, wrow0 + 128, E * H - 1, FF, k0, tid);
            cp_tile64(o + 6 * TB, g_w2l, wrow0,       E * H - 1, FF, k0, tid);
            cp_tile64(o + 7 * TB, g_w2l, wrow0 + 128, E * H - 1, FF, k0, tid);
            CP_COMMIT();
            CP_WAIT0();
            __syncthreads();
        }
    }
#pragma unroll
    for (int b = 0; b < 3; b++) {
        int tot = (NCH - b + 2) / 3;
        if (tot > 0) MBAR_WAIT(sb + 8 + b * 8, (tot - 1) & 1);
    }
    TC_FENCE_AFTER();

    int rh = wid >> 2, sub = wid & 3;
    int rloc = rh * 128 + sub * 32 + lid;
    bool valid = (row0 + rloc) < cnt;
    int ts = 0; float w = 0.f;
    if (valid) { ts = g_list[e * T_MAX + row0 + rloc]; w = g_wts[ts]; }
    float* yrow = g_ybuf + (size_t)ts * H + n0;
#pragma unroll
    for (int c0 = 0; c0 < 256; c0 += 32) {
        uint32_t d[32];
        TC_LD_X32(d, tm + rh * 256 + c0);
        TC_WAIT_LD();
        if (valid) {
            float4* dst = (float4*)(yrow + c0);
#pragma unroll
            for (int q = 0; q < 8; q++)
                dst[q] = make_float4(w * __uint_as_float(d[4 * q]), w * __uint_as_float(d[4 * q + 1]),
                                     w * __uint_as_float(d[4 * q + 2]), w * __uint_as_float(d[4 * q + 3]));
        }
    }
    TC_FENCE_BEFORE();
    __syncthreads();
    if (wid == 0) { TC_RELINQ(); TC_DEALLOC(tm, 512); }
#endif
}

__global__ void k_combine(float* __restrict__ out, int T) {
    int i = blockIdx.x * blockDim.x + threadIdx.x;
    int total = T * (H / 4);
    if (i >= total) return;
    int t = i / (H / 4);
    int h4 = i - t * (H / 4);
    const float4* yb = (const float4*)g_ybuf;
    float4 a = yb[(size_t)(2 * t) * (H / 4) + h4];
    float4 b = yb[(size_t)(2 * t + 1) * (H / 4) + h4];
    ((float4*)out)[i] = make_float4(a.x + b.x, a.y + b.y, a.z + b.z, a.w + b.w);
}

// ---------------- launch ----------------
extern "C" void kernel_launch(void* const* d_in, const int* in_sizes, int n_in,
                              void* d_out, int out_size) {
    const float* x;
    const float* gate;
    if (in_sizes[0] > in_sizes[1]) { x = (const float*)d_in[0]; gate = (const float*)d_in[1]; }
    else                           { gate = (const float*)d_in[0]; x = (const float*)d_in[1]; }
    const float* w1 = (const float*)d_in[2];
    const float* w2 = (const float*)d_in[3];
    const float* w3 = (const float*)d_in[4];
    int T = (in_sizes[0] > in_sizes[1] ? in_sizes[0] : in_sizes[1]) / H;

    float* out = (float*)d_out;
    float* logits_out = out + (size_t)T * H;

    int smem = SM_T + 3 * 8 * TB;  // 197,632
    cudaFuncSetAttribute(k_mma13, cudaFuncAttributeMaxDynamicSharedMemorySize, smem);
    cudaFuncSetAttribute(k_mma2,  cudaFuncAttributeMaxDynamicSharedMemorySize, smem);

    __nv_bfloat16 *w1h, *w1l, *w3h, *w3l, *w2h, *w2l;
    cudaGetSymbolAddress((void**)&w1h, g_w1h); cudaGetSymbolAddress((void**)&w1l, g_w1l);
    cudaGetSymbolAddress((void**)&w3h, g_w3h); cudaGetSymbolAddress((void**)&w3l, g_w3l);
    cudaGetSymbolAddress((void**)&w2h, g_w2h); cudaGetSymbolAddress((void**)&w2l, g_w2l);

    k_zero<<<1, 32>>>();
    k_router<<<(T + 7) / 8, 256>>>(x, gate, logits_out, T);
    k_base<<<1, 1>>>();

    long n8 = (long)E * FF * H / 8;
    int sblk = (int)((n8 + 255) / 256);
    k_split8<<<sblk, 256>>>(w1, w1h, w1l, n8);
    k_split8<<<sblk, 256>>>(w3, w3h, w3l, n8);
    k_split8<<<sblk, 256>>>(w2, w2h, w2l, n8);
    k_gather<<<2 * T, 128>>>(x, 2 * T);

    int ytiles = (2 * T + 255) / 256;
    dim3 g13(FF / 128, ytiles, E);
    k_mma13<<<g13, 256, smem>>>();
    dim3 g2(H / 256, ytiles, E);
    k_mma2<<<g2, 256, smem>>>();

    k_combine<<<(T * (H / 4) + 255) / 256, 256>>>(out, T);
}

// round 8
// speedup vs baseline: 13.5975x; 1.1639x over previous
#include <cuda_runtime.h>
#include <cuda_bf16.h>
#include <cstdint>
#include <stdint.h>
#include <math.h>

#define H      1024
#define FF     4096
#define E      8
#define T_MAX  8192
#define NROWS  (T_MAX * 2)
#define NROWSP 18432          // padded rows (per-expert base aligned to 256)
#define KC     32             // K-chunk
#define TB     8192           // one tile: 128 rows x 64 bytes (SW64), contiguous in global
#define NKC_H  (H / KC)       // 32
#define NKC_F  (FF / KC)      // 128

#if defined(__CUDA_ARCH_FEAT_SM103_ALL) || defined(__CUDA_ARCH_FEAT_SM100_ALL)
#define TC_OK 1
#else
#define TC_OK 0
#endif

// ---------------- device scratch ----------------
__device__ int   g_counts[E];
__device__ int   g_base[E];    // unpadded cumulative (for token->slot lookup)
__device__ int   g_pbase[E];   // padded-to-256 cumulative (tile-aligned rows)
__device__ int   g_list[E * T_MAX];
__device__ float g_wts[T_MAX * 2];
// all tiled buffers: tile(tr, kc) contiguous 8KB at ((tr*NKC + kc) * 8192)
__device__ __nv_bfloat16 g_ax_hi[(size_t)NROWSP * H];
__device__ __nv_bfloat16 g_ax_lo[(size_t)NROWSP * H];
__device__ __nv_bfloat16 g_w1h[(size_t)E * FF * H];
__device__ __nv_bfloat16 g_w1l[(size_t)E * FF * H];
__device__ __nv_bfloat16 g_w3h[(size_t)E * FF * H];
__device__ __nv_bfloat16 g_w3l[(size_t)E * FF * H];
__device__ __nv_bfloat16 g_w2h[(size_t)E * H * FF];
__device__ __nv_bfloat16 g_w2l[(size_t)E * H * FF];
__device__ __nv_bfloat16 g_act_hi[(size_t)NROWSP * FF];
__device__ __nv_bfloat16 g_act_lo[(size_t)NROWSP * FF];
__device__ float g_ybuf[(size_t)NROWS * H];

// ---------------- PTX helpers ----------------
__device__ __forceinline__ uint32_t smem_u32(const void* p) {
    uint32_t a;
    asm("{ .reg .u64 t; cvta.to.shared.u64 t, %1; cvt.u32.u64 %0, t; }" : "=r"(a) : "l"(p));
    return a;
}
#define MBAR_INIT(a, c) asm volatile("mbarrier.init.shared.b64 [%0], %1;" :: "r"((uint32_t)(a)), "r"((uint32_t)(c)) : "memory")
#define MBAR_EXPECT(a, n) asm volatile("mbarrier.arrive.expect_tx.shared.b64 _, [%0], %1;" :: "r"((uint32_t)(a)), "r"((uint32_t)(n)) : "memory")
#define MBAR_WAIT(a, ph) do { \
    uint32_t _m = (uint32_t)(a), _p = (uint32_t)(ph), _d; \
    asm volatile("{\n\t.reg .pred p;\n\tmbarrier.try_wait.parity.acquire.cta.shared::cta.b64 p, [%1], %2;\n\tselp.b32 %0,1,0,p;\n\t}" \
        : "=r"(_d) : "r"(_m), "r"(_p) : "memory"); \
    if (!_d) { asm volatile("{\n\t.reg .pred P1;\n\tWL_%=:\n\t" \
        "mbarrier.try_wait.parity.acquire.cta.shared::cta.b64 P1, [%0], %1, 0x989680;\n\t" \
        "@P1 bra.uni WD_%=;\n\tbra.uni WL_%=;\n\tWD_%=:\n\t}" :: "r"(_m), "r"(_p) : "memory"); } \
} while (0)

#if TC_OK
#define BULK(d, s, mb) asm volatile( \
    "cp.async.bulk.shared::cta.global.mbarrier::complete_tx::bytes [%0], [%1], %2, [%3];" \
    :: "r"((uint32_t)(d)), "l"(s), "r"(8192u), "r"((uint32_t)(mb)) : "memory")
#define TC_ALLOC(sa, n)   asm volatile("tcgen05.alloc.cta_group::1.sync.aligned.shared::cta.b32 [%0], %1;" :: "r"((uint32_t)(sa)), "r"((uint32_t)(n)) : "memory")
#define TC_DEALLOC(tm, n) asm volatile("tcgen05.dealloc.cta_group::1.sync.aligned.b32 %0, %1;" :: "r"(tm), "r"((uint32_t)(n)))
#define TC_RELINQ()       asm volatile("tcgen05.relinquish_alloc_permit.cta_group::1.sync.aligned;")
#define TC_COMMIT(mb)     asm volatile("tcgen05.commit.cta_group::1.mbarrier::arrive::one.shared::cluster.b64 [%0];" :: "r"((uint32_t)(mb)) : "memory")
#define TC_FENCE_AFTER()  asm volatile("tcgen05.fence::after_thread_sync;" ::: "memory")
#define TC_FENCE_BEFORE() asm volatile("tcgen05.fence::before_thread_sync;" ::: "memory")
#define TC_WAIT_LD()      asm volatile("tcgen05.wait::ld.sync.aligned;" ::: "memory")
#define TC_LD_X32(r, ta) \
    asm volatile("tcgen05.ld.sync.aligned.32x32b.x32.b32 " \
        "{%0,%1,%2,%3,%4,%5,%6,%7,%8,%9,%10,%11,%12,%13,%14,%15," \
        "%16,%17,%18,%19,%20,%21,%22,%23,%24,%25,%26,%27,%28,%29,%30,%31}, [%32];" \
        : "=r"((r)[0]), "=r"((r)[1]), "=r"((r)[2]), "=r"((r)[3]), "=r"((r)[4]), "=r"((r)[5]), "=r"((r)[6]), "=r"((r)[7]), \
          "=r"((r)[8]), "=r"((r)[9]), "=r"((r)[10]), "=r"((r)[11]), "=r"((r)[12]), "=r"((r)[13]), "=r"((r)[14]), "=r"((r)[15]), \
          "=r"((r)[16]), "=r"((r)[17]), "=r"((r)[18]), "=r"((r)[19]), "=r"((r)[20]), "=r"((r)[21]), "=r"((r)[22]), "=r"((r)[23]), \
          "=r"((r)[24]), "=r"((r)[25]), "=r"((r)[26]), "=r"((r)[27]), "=r"((r)[28]), "=r"((r)[29]), "=r"((r)[30]), "=r"((r)[31]) \
        : "r"(ta))

// SW64 K-major descriptor: layout=4, version=1, SBO=32 (512B per 8-row group), LBO=1
static constexpr uint64_t DESC_SW64 =
    (uint64_t(4) << 61) | (uint64_t(1) << 46) | (uint64_t(32) << 32) | (uint64_t(1) << 16);
#define MK_DESC(a) (DESC_SW64 | ((uint64_t)((a) >> 4) & 0x3FFF))
// idesc kind::f16: F32 out, BF16 a/b, M=128, N=256 (B spans two adjacent tiles)
#define IDESC256 ((1u << 4) | (1u << 7) | (1u << 10) | (32u << 17) | (8u << 24))

__device__ __forceinline__ void mma256(uint32_t d, uint64_t a, uint64_t b, uint32_t en) {
    asm volatile("{\n\t.reg .pred p;\n\tsetp.ne.u32 p, %4, 0;\n\t"
        "tcgen05.mma.cta_group::1.kind::f16 [%0], %1, %2, %3, {%5,%5,%5,%5}, p;\n\t}"
        :: "r"(d), "l"(a), "l"(b), "r"(IDESC256), "r"(en), "r"(0u) : "memory");
}
#endif  // TC_OK

__device__ __forceinline__ uint32_t pack_hi(float a, float b, uint32_t& lo) {
    __nv_bfloat16 h0 = __float2bfloat16(a), h1 = __float2bfloat16(b);
    __nv_bfloat16 l0 = __float2bfloat16(a - __bfloat162float(h0));
    __nv_bfloat16 l1 = __float2bfloat16(b - __bfloat162float(h1));
    lo = (uint32_t)__bfloat16_as_ushort(l0) | ((uint32_t)__bfloat16_as_ushort(l1) << 16);
    return (uint32_t)__bfloat16_as_ushort(h0) | ((uint32_t)__bfloat16_as_ushort(h1) << 16);
}

// ---------------- routing ----------------
__global__ void k_zero() { if (threadIdx.x < E) g_counts[threadIdx.x] = 0; }

__global__ void k_router(const float* __restrict__ x, const float* __restrict__ gate,
                         float* __restrict__ logits_out, int T) {
    __shared__ float sg[E * H];
    for (int i = threadIdx.x; i < E * H; i += blockDim.x) sg[i] = gate[i];
    __syncthreads();
    int warp = threadIdx.x >> 5, lane = threadIdx.x & 31;
    int t = blockIdx.x * 8 + warp;
    if (t >= T) return;
    const float* xr = x + (size_t)t * H;
    float acc[E];
#pragma unroll
    for (int e = 0; e < E; e++) acc[e] = 0.f;
    for (int k = lane; k < H; k += 32) {
        float xv = xr[k];
#pragma unroll
        for (int e = 0; e < E; e++) acc[e] += xv * sg[e * H + k];
    }
#pragma unroll
    for (int e = 0; e < E; e++)
#pragma unroll
        for (int o = 16; o > 0; o >>= 1) acc[e] += __shfl_down_sync(0xffffffffu, acc[e], o);
    if (lane == 0) {
#pragma unroll
        for (int e = 0; e < E; e++) logits_out[(size_t)t * E + e] = acc[e];
        int e0 = 0; float l0 = acc[0];
#pragma unroll
        for (int e = 1; e < E; e++) if (acc[e] > l0) { l0 = acc[e]; e0 = e; }
        int e1 = -1; float l1 = -1e30f;
#pragma unroll
        for (int e = 0; e < E; e++) if (e != e0 && acc[e] > l1) { l1 = acc[e]; e1 = e; }
        float s = 0.f, pe[E];
#pragma unroll
        for (int e = 0; e < E; e++) { pe[e] = expf(acc[e] - l0); s += pe[e]; }
        float p0 = pe[e0] / s, p1 = pe[e1] / s;
        float inv = 1.f / (p0 + p1);
        int q0 = atomicAdd(&g_counts[e0], 1);
        g_list[e0 * T_MAX + q0] = (t << 1);
        g_wts[(t << 1)] = p0 * inv;
        int q1 = atomicAdd(&g_counts[e1], 1);
        g_list[e1 * T_MAX + q1] = (t << 1) | 1;
        g_wts[(t << 1) | 1] = p1 * inv;
    }
}

__global__ void k_base() {
    if (threadIdx.x == 0) {
        int s = 0, ps = 0;
#pragma unroll
        for (int e = 0; e < E; e++) {
            g_base[e] = s;  g_pbase[e] = ps;
            s += g_counts[e];
            ps += (g_counts[e] + 255) & ~255;
        }
    }
}

// fp32 -> bf16 hi/lo, written pre-tiled+pre-swizzled (8 elems = one 16B chunk per thread)
__global__ void k_split8(const float* __restrict__ src, __nv_bfloat16* __restrict__ hi,
                         __nv_bfloat16* __restrict__ lo, long n8, int K, int nkc) {
    long i = (long)blockIdx.x * blockDim.x + threadIdx.x;
    if (i >= n8) return;
    long f = i * 8;
    int row = (int)(f / K), k0 = (int)(f % K);
    int kc = k0 >> 5, c = (k0 & 31) >> 3;
    int rr = row & 127, tr = row >> 7;
    size_t off = ((size_t)tr * nkc + kc) * TB + (size_t)rr * 64 + ((c ^ ((rr >> 1) & 3)) << 4);
    const float4* s4 = (const float4*)(src + f);
    float4 a = s4[0], b = s4[1];
    float v[8] = {a.x, a.y, a.z, a.w, b.x, b.y, b.z, b.w};
    uint32_t ph[4], pl[4];
#pragma unroll
    for (int j = 0; j < 4; j++) ph[j] = pack_hi(v[2 * j], v[2 * j + 1], pl[j]);
    *(uint4*)((char*)hi + off) = make_uint4(ph[0], ph[1], ph[2], ph[3]);
    *(uint4*)((char*)lo + off) = make_uint4(pl[0], pl[1], pl[2], pl[3]);
}

// gather x rows into expert-grouped (padded) tiled hi/lo; 128 threads, 8 cols each
__global__ void k_gather(const float* __restrict__ x, int total) {
    int g = blockIdx.x;
    if (g >= total) return;
    int e = 0;
#pragma unroll
    for (int k = 1; k < E; k++) if (g >= g_base[k]) e = k;
    int pos = g - g_base[e];
    int tok = g_list[e * T_MAX + pos] >> 1;
    int prow = g_pbase[e] + pos;
    int rr = prow & 127, tr = prow >> 7;
    int tid = threadIdx.x;                 // 0..127
    int kc = tid >> 2, c = tid & 3;
    size_t off = ((size_t)tr * NKC_H + kc) * TB + (size_t)rr * 64 + ((c ^ ((rr >> 1) & 3)) << 4);
    const float4* src = (const float4*)(x + (size_t)tok * H + tid * 8);
    float4 a = src[0], b = src[1];
    float v[8] = {a.x, a.y, a.z, a.w, b.x, b.y, b.z, b.w};
    uint32_t ph[4], pl[4];
#pragma unroll
    for (int j = 0; j < 4; j++) ph[j] = pack_hi(v[2 * j], v[2 * j + 1], pl[j]);
    *(uint4*)((char*)g_ax_hi + off) = make_uint4(ph[0], ph[1], ph[2], ph[3]);
    *(uint4*)((char*)g_ax_lo + off) = make_uint4(pl[0], pl[1], pl[2], pl[3]);
}

#define SM_T 1024

#if TC_OK
// stage fill for gemm13: 8 bulk copies of 8KB
__device__ __forceinline__ void ld13(uint32_t sb, int buf, int kc, int trA, int trW) {
    uint32_t mb = sb + 8 + buf * 8;
    uint32_t dst = sb + SM_T + buf * 8 * TB;
    MBAR_EXPECT(mb, 8 * TB);
    size_t a0 = ((size_t)trA * NKC_H + kc) * TB;
    size_t a1 = ((size_t)(trA + 1) * NKC_H + kc) * TB;
    size_t w  = ((size_t)trW * NKC_H + kc) * TB;
    BULK(dst + 0 * TB, (const char*)g_ax_hi + a0, mb);
    BULK(dst + 1 * TB, (const char*)g_ax_lo + a0, mb);
    BULK(dst + 2 * TB, (const char*)g_ax_hi + a1, mb);
    BULK(dst + 3 * TB, (const char*)g_ax_lo + a1, mb);
    BULK(dst + 4 * TB, (const char*)g_w1h + w, mb);
    BULK(dst + 5 * TB, (const char*)g_w3h + w, mb);
    BULK(dst + 6 * TB, (const char*)g_w1l + w, mb);
    BULK(dst + 7 * TB, (const char*)g_w3l + w, mb);
}
// stage fill for gemm2
__device__ __forceinline__ void ld2(uint32_t sb, int buf, int kc, int trA, int trW) {
    uint32_t mb = sb + 8 + buf * 8;
    uint32_t dst = sb + SM_T + buf * 8 * TB;
    MBAR_EXPECT(mb, 8 * TB);
    size_t a0 = ((size_t)trA * NKC_F + kc) * TB;
    size_t a1 = ((size_t)(trA + 1) * NKC_F + kc) * TB;
    size_t wa = ((size_t)trW * NKC_F + kc) * TB;
    size_t wb = ((size_t)(trW + 1) * NKC_F + kc) * TB;
    BULK(dst + 0 * TB, (const char*)g_act_hi + a0, mb);
    BULK(dst + 1 * TB, (const char*)g_act_lo + a0, mb);
    BULK(dst + 2 * TB, (const char*)g_act_hi + a1, mb);
    BULK(dst + 3 * TB, (const char*)g_act_lo + a1, mb);
    BULK(dst + 4 * TB, (const char*)g_w2h + wa, mb);
    BULK(dst + 5 * TB, (const char*)g_w2h + wb, mb);
    BULK(dst + 6 * TB, (const char*)g_w2l + wa, mb);
    BULK(dst + 7 * TB, (const char*)g_w2l + wb, mb);
}
#endif

// ---------------- tcgen05 GEMM13: BM=256, BN=128, 3-stage bulk pipeline ----------------
__global__ __launch_bounds__(256, 1) void k_mma13() {
#if TC_OK
    int e = blockIdx.z;
    int cnt = g_counts[e];
    int row0 = blockIdx.y * 256;
    if (row0 >= cnt) return;
    int n0 = blockIdx.x * 128;
    int grow0 = g_pbase[e] + row0;
    int trA = grow0 >> 7;
    int trW = (e * FF + n0) >> 7;

    extern __shared__ char sm[];
    uint32_t sb = smem_u32(sm);
    int tid = threadIdx.x, wid = tid >> 5, lid = tid & 31;

    if (wid == 0) TC_ALLOC(sb, 512);
    if (tid == 0) {
#pragma unroll
        for (int b = 0; b < 3; b++) { MBAR_INIT(sb + 8 + b * 8, 1); MBAR_INIT(sb + 32 + b * 8, 1); }
    }
    __syncthreads();
    uint32_t tm;
    asm volatile("ld.shared.b32 %0, [%1];" : "=r"(tm) : "r"(sb));

    const int NCH = NKC_H;  // 32
    if (tid == 0) {
        ld13(sb, 0, 0, trA, trW);
        ld13(sb, 1, 1, trA, trW);
        for (int i = 0; i < NCH; i++) {
            int b = i % 3;
            MBAR_WAIT(sb + 8 + b * 8, (i / 3) & 1);           // load complete
            uint32_t tb = sb + SM_T + b * 8 * TB;
            uint64_t dAh0 = MK_DESC(tb),          dAl0 = MK_DESC(tb + TB);
            uint64_t dAh1 = MK_DESC(tb + 2 * TB), dAl1 = MK_DESC(tb + 3 * TB);
            uint64_t dWh  = MK_DESC(tb + 4 * TB), dWl  = MK_DESC(tb + 6 * TB);
#pragma unroll
            for (int ks = 0; ks < 2; ks++) {
                uint64_t o = (uint64_t)(2 * ks);
                uint32_t en = (i > 0 || ks > 0) ? 1u : 0u;
                mma256(tm,       dAh0 + o, dWh + o, en);
                mma256(tm,       dAh0 + o, dWl + o, 1);
                mma256(tm,       dAl0 + o, dWh + o, 1);
                mma256(tm + 256, dAh1 + o, dWh + o, en);
                mma256(tm + 256, dAh1 + o, dWl + o, 1);
                mma256(tm + 256, dAl1 + o, dWh + o, 1);
            }
            TC_COMMIT(sb + 32 + b * 8);
            if (i + 2 < NCH) {
                int nb = (i + 2) % 3;
                if (i >= 1) MBAR_WAIT(sb + 32 + nb * 8, ((i - 1) / 3) & 1);  // MMA(i-1) done
                ld13(sb, nb, i + 2, trA, trW);
            }
        }
        for (int c = NCH - 3; c < NCH; c++)                    // drain final commits
            MBAR_WAIT(sb + 32 + (c % 3) * 8, (c / 3) & 1);
    }
    __syncthreads();
    TC_FENCE_AFTER();

    // epilogue: silu(d1)*d3 -> act (tiled hi/lo)
    int rh = wid >> 2, sub = wid & 3;
    int rloc = rh * 128 + sub * 32 + lid;
    bool valid = (row0 + rloc) < cnt;
    int prow = grow0 + rloc;
    int rr = prow & 127, tr = prow >> 7, sw = (rr >> 1) & 3;
#pragma unroll
    for (int c0 = 0; c0 < 128; c0 += 32) {
        uint32_t d1[32], d3[32];
        TC_LD_X32(d1, tm + rh * 256 + c0);
        TC_LD_X32(d3, tm + rh * 256 + 128 + c0);
        TC_WAIT_LD();
        if (valid) {
            uint32_t ph[16], pl[16];
#pragma unroll
            for (int j = 0; j < 16; j++) {
                float h0 = __uint_as_float(d1[2 * j]),     v0 = __uint_as_float(d3[2 * j]);
                float h1 = __uint_as_float(d1[2 * j + 1]), v1 = __uint_as_float(d3[2 * j + 1]);
                float a0 = (h0 / (1.f + __expf(-h0))) * v0;
                float a1 = (h1 / (1.f + __expf(-h1))) * v1;
                ph[j] = pack_hi(a0, a1, pl[j]);
            }
            int kc = (n0 >> 5) + (c0 >> 5);
            size_t tbo = ((size_t)tr * NKC_F + kc) * TB + (size_t)rr * 64;
#pragma unroll
            for (int q = 0; q < 4; q++) {
                size_t o = tbo + ((q ^ sw) << 4);
                *(uint4*)((char*)g_act_hi + o) = make_uint4(ph[4 * q], ph[4 * q + 1], ph[4 * q + 2], ph[4 * q + 3]);
                *(uint4*)((char*)g_act_lo + o) = make_uint4(pl[4 * q], pl[4 * q + 1], pl[4 * q + 2], pl[4 * q + 3]);
            }
        }
    }
    TC_FENCE_BEFORE();
    __syncthreads();
    if (wid == 0) { TC_RELINQ(); TC_DEALLOC(tm, 512); }
#endif
}

// ---------------- tcgen05 GEMM2: BM=256, BN=256, 3-stage bulk pipeline ----------------
__global__ __launch_bounds__(256, 1) void k_mma2() {
#if TC_OK
    int e = blockIdx.z;
    int cnt = g_counts[e];
    int row0 = blockIdx.y * 256;
    if (row0 >= cnt) return;
    int n0 = blockIdx.x * 256;
    int grow0 = g_pbase[e] + row0;
    int trA = grow0 >> 7;
    int trW = (e * H + n0) >> 7;

    extern __shared__ char sm[];
    uint32_t sb = smem_u32(sm);
    int tid = threadIdx.x, wid = tid >> 5, lid = tid & 31;

    if (wid == 0) TC_ALLOC(sb, 512);
    if (tid == 0) {
#pragma unroll
        for (int b = 0; b < 3; b++) { MBAR_INIT(sb + 8 + b * 8, 1); MBAR_INIT(sb + 32 + b * 8, 1); }
    }
    __syncthreads();
    uint32_t tm;
    asm volatile("ld.shared.b32 %0, [%1];" : "=r"(tm) : "r"(sb));

    const int NCH = NKC_F;  // 128
    if (tid == 0) {
        ld2(sb, 0, 0, trA, trW);
        ld2(sb, 1, 1, trA, trW);
        for (int i = 0; i < NCH; i++) {
            int b = i % 3;
            MBAR_WAIT(sb + 8 + b * 8, (i / 3) & 1);
            uint32_t tb = sb + SM_T + b * 8 * TB;
            uint64_t dAh0 = MK_DESC(tb),          dAl0 = MK_DESC(tb + TB);
            uint64_t dAh1 = MK_DESC(tb + 2 * TB), dAl1 = MK_DESC(tb + 3 * TB);
            uint64_t dWh  = MK_DESC(tb + 4 * TB), dWl  = MK_DESC(tb + 6 * TB);
#pragma unroll
            for (int ks = 0; ks < 2; ks++) {
                uint64_t o = (uint64_t)(2 * ks);
                uint32_t en = (i > 0 || ks > 0) ? 1u : 0u;
                mma256(tm,       dAh0 + o, dWh + o, en);
                mma256(tm,       dAh0 + o, dWl + o, 1);
                mma256(tm,       dAl0 + o, dWh + o, 1);
                mma256(tm + 256, dAh1 + o, dWh + o, en);
                mma256(tm + 256, dAh1 + o, dWl + o, 1);
                mma256(tm + 256, dAl1 + o, dWh + o, 1);
            }
            TC_COMMIT(sb + 32 + b * 8);
            if (i + 2 < NCH) {
                int nb = (i + 2) % 3;
                if (i >= 1) MBAR_WAIT(sb + 32 + nb * 8, ((i - 1) / 3) & 1);
                ld2(sb, nb, i + 2, trA, trW);
            }
        }
        for (int c = NCH - 3; c < NCH; c++)
            MBAR_WAIT(sb + 32 + (c % 3) * 8, (c / 3) & 1);
    }
    __syncthreads();
    TC_FENCE_AFTER();

    int rh = wid >> 2, sub = wid & 3;
    int rloc = rh * 128 + sub * 32 + lid;
    bool valid = (row0 + rloc) < cnt;
    int ts = 0; float w = 0.f;
    if (valid) { ts = g_list[e * T_MAX + row0 + rloc]; w = g_wts[ts]; }
    float* yrow = g_ybuf + (size_t)ts * H + n0;
#pragma unroll
    for (int c0 = 0; c0 < 256; c0 += 32) {
        uint32_t d[32];
        TC_LD_X32(d, tm + rh * 256 + c0);
        TC_WAIT_LD();
        if (valid) {
            float4* dst = (float4*)(yrow + c0);
#pragma unroll
            for (int q = 0; q < 8; q++)
                dst[q] = make_float4(w * __uint_as_float(d[4 * q]), w * __uint_as_float(d[4 * q + 1]),
                                     w * __uint_as_float(d[4 * q + 2]), w * __uint_as_float(d[4 * q + 3]));
        }
    }
    TC_FENCE_BEFORE();
    __syncthreads();
    if (wid == 0) { TC_RELINQ(); TC_DEALLOC(tm, 512); }
#endif
}

__global__ void k_combine(float* __restrict__ out, int T) {
    int i = blockIdx.x * blockDim.x + threadIdx.x;
    int total = T * (H / 4);
    if (i >= total) return;
    int t = i / (H / 4);
    int h4 = i - t * (H / 4);
    const float4* yb = (const float4*)g_ybuf;
    float4 a = yb[(size_t)(2 * t) * (H / 4) + h4];
    float4 b = yb[(size_t)(2 * t + 1) * (H / 4) + h4];
    ((float4*)out)[i] = make_float4(a.x + b.x, a.y + b.y, a.z + b.z, a.w + b.w);
}

// ---------------- launch ----------------
extern "C" void kernel_launch(void* const* d_in, const int* in_sizes, int n_in,
                              void* d_out, int out_size) {
    const float* x;
    const float* gate;
    if (in_sizes[0] > in_sizes[1]) { x = (const float*)d_in[0]; gate = (const float*)d_in[1]; }
    else                           { gate = (const float*)d_in[0]; x = (const float*)d_in[1]; }
    const float* w1 = (const float*)d_in[2];
    const float* w2 = (const float*)d_in[3];
    const float* w3 = (const float*)d_in[4];
    int T = (in_sizes[0] > in_sizes[1] ? in_sizes[0] : in_sizes[1]) / H;

    float* out = (float*)d_out;
    float* logits_out = out + (size_t)T * H;

    int smem = SM_T + 3 * 8 * TB;  // 197,632
    cudaFuncSetAttribute(k_mma13, cudaFuncAttributeMaxDynamicSharedMemorySize, smem);
    cudaFuncSetAttribute(k_mma2,  cudaFuncAttributeMaxDynamicSharedMemorySize, smem);

    __nv_bfloat16 *w1h, *w1l, *w3h, *w3l, *w2h, *w2l;
    cudaGetSymbolAddress((void**)&w1h, g_w1h); cudaGetSymbolAddress((void**)&w1l, g_w1l);
    cudaGetSymbolAddress((void**)&w3h, g_w3h); cudaGetSymbolAddress((void**)&w3l, g_w3l);
    cudaGetSymbolAddress((void**)&w2h, g_w2h); cudaGetSymbolAddress((void**)&w2l, g_w2l);

    k_zero<<<1, 32>>>();
    k_router<<<(T + 7) / 8, 256>>>(x, gate, logits_out, T);
    k_base<<<1, 1>>>();

    long n8 = (long)E * FF * H / 8;
    int sblk = (int)((n8 + 255) / 256);
    k_split8<<<sblk, 256>>>(w1, w1h, w1l, n8, H, NKC_H);
    k_split8<<<sblk, 256>>>(w3, w3h, w3l, n8, H, NKC_H);
    k_split8<<<sblk, 256>>>(w2, w2h, w2l, n8, FF, NKC_F);
    k_gather<<<2 * T, 128>>>(x, 2 * T);

    int ytiles = (2 * T + 255) / 256;
    dim3 g13(FF / 128, ytiles, E);
    k_mma13<<<g13, 256, smem>>>();
    dim3 g2(H / 256, ytiles, E);
    k_mma2<<<g2, 256, smem>>>();

    k_combine<<<(T * (H / 4) + 255) / 256, 256>>>(out, T);
}

// round 10
// speedup vs baseline: 15.1095x; 1.1112x over previous
#include <cuda_runtime.h>
#include <cuda_bf16.h>
#include <cstdint>
#include <stdint.h>
#include <math.h>

#define H      1024
#define FF     4096
#define E      8
#define T_MAX  8192
#define NROWS  (T_MAX * 2)
#define NROWSP 20480          // padded rows (per-expert base aligned to 512)
#define KC     32             // K-chunk
#define TB     8192           // one tile: 128 rows x 64 bytes (SW64), contiguous in global
#define NKC_H  (H / KC)       // 32
#define NKC_F  (FF / KC)      // 128

#if defined(__CUDA_ARCH_FEAT_SM103_ALL) || defined(__CUDA_ARCH_FEAT_SM100_ALL)
#define TC_OK 1
#else
#define TC_OK 0
#endif

// ---------------- device scratch ----------------
__device__ int   g_counts[E];
__device__ int   g_base[E];
__device__ int   g_pbase[E];   // padded-to-512 cumulative
__device__ int   g_list[E * T_MAX];
__device__ float g_wts[T_MAX * 2];
__device__ __nv_bfloat16 g_ax_hi[(size_t)NROWSP * H];
__device__ __nv_bfloat16 g_ax_lo[(size_t)NROWSP * H];
__device__ __nv_bfloat16 g_w1h[(size_t)E * FF * H];
__device__ __nv_bfloat16 g_w1l[(size_t)E * FF * H];
__device__ __nv_bfloat16 g_w3h[(size_t)E * FF * H];
__device__ __nv_bfloat16 g_w3l[(size_t)E * FF * H];
__device__ __nv_bfloat16 g_w2h[(size_t)E * H * FF];
__device__ __nv_bfloat16 g_w2l[(size_t)E * H * FF];
__device__ __nv_bfloat16 g_act_hi[(size_t)NROWSP * FF];
__device__ __nv_bfloat16 g_act_lo[(size_t)NROWSP * FF];
__device__ float g_ybuf[(size_t)NROWS * H];

// ---------------- PTX helpers ----------------
__device__ __forceinline__ uint32_t smem_u32(const void* p) {
    uint32_t a;
    asm("{ .reg .u64 t; cvta.to.shared.u64 t, %1; cvt.u32.u64 %0, t; }" : "=r"(a) : "l"(p));
    return a;
}
__device__ __forceinline__ uint32_t cta_rank() {
    uint32_t r; asm("mov.u32 %0, %%cluster_ctarank;" : "=r"(r)); return r;
}
#define MBAR_INIT(a, c) asm volatile("mbarrier.init.shared.b64 [%0], %1;" :: "r"((uint32_t)(a)), "r"((uint32_t)(c)) : "memory")
#define MBAR_EXPECT(a, n) asm volatile("mbarrier.arrive.expect_tx.shared.b64 _, [%0], %1;" :: "r"((uint32_t)(a)), "r"((uint32_t)(n)) : "memory")
#define ARRIVE_REMOTE0(local) asm volatile("{\n\t.reg .b32 r;\n\tmapa.shared::cluster.u32 r, %0, 0;\n\tmbarrier.arrive.shared::cluster.b64 _, [r];\n\t}" :: "r"((uint32_t)(local)) : "memory")
#define CLUSTER_SYNC() do { \
    asm volatile("barrier.cluster.arrive.aligned;" ::: "memory"); \
    asm volatile("barrier.cluster.wait.aligned;" ::: "memory"); \
} while (0)
#define MBAR_WAIT(a, ph) do { \
    uint32_t _m = (uint32_t)(a), _p = (uint32_t)(ph), _d; \
    asm volatile("{\n\t.reg .pred p;\n\tmbarrier.try_wait.parity.acquire.cta.shared::cta.b64 p, [%1], %2;\n\tselp.b32 %0,1,0,p;\n\t}" \
        : "=r"(_d) : "r"(_m), "r"(_p) : "memory"); \
    if (!_d) { asm volatile("{\n\t.reg .pred P1;\n\tWL_%=:\n\t" \
        "mbarrier.try_wait.parity.acquire.cta.shared::cta.b64 P1, [%0], %1, 0x989680;\n\t" \
        "@P1 bra.uni WD_%=;\n\tbra.uni WL_%=;\n\tWD_%=:\n\t}" :: "r"(_m), "r"(_p) : "memory"); } \
} while (0)

#if TC_OK
#define BULK(d, s, mb) asm volatile( \
    "cp.async.bulk.shared::cta.global.mbarrier::complete_tx::bytes [%0], [%1], %2, [%3];" \
    :: "r"((uint32_t)(d)), "l"(s), "r"(8192u), "r"((uint32_t)(mb)) : "memory")
#define TC_ALLOC_CG2(sa, n)   asm volatile("tcgen05.alloc.cta_group::2.sync.aligned.shared::cta.b32 [%0], %1;" :: "r"((uint32_t)(sa)), "r"((uint32_t)(n)) : "memory")
#define TC_DEALLOC_CG2(tm, n) asm volatile("tcgen05.dealloc.cta_group::2.sync.aligned.b32 %0, %1;" :: "r"(tm), "r"((uint32_t)(n)))
#define TC_RELINQ_CG2()       asm volatile("tcgen05.relinquish_alloc_permit.cta_group::2.sync.aligned;")
#define TC_COMMIT_MC2(mb, mask) asm volatile( \
    "tcgen05.commit.cta_group::2.mbarrier::arrive::one.shared::cluster.multicast::cluster.b64 [%0], %1;" \
    :: "r"((uint32_t)(mb)), "h"((uint16_t)(mask)) : "memory")
#define TC_FENCE_AFTER()  asm volatile("tcgen05.fence::after_thread_sync;" ::: "memory")
#define TC_FENCE_BEFORE() asm volatile("tcgen05.fence::before_thread_sync;" ::: "memory")
#define TC_WAIT_LD()      asm volatile("tcgen05.wait::ld.sync.aligned;" ::: "memory")
#define TC_LD_X32(r, ta) \
    asm volatile("tcgen05.ld.sync.aligned.32x32b.x32.b32 " \
        "{%0,%1,%2,%3,%4,%5,%6,%7,%8,%9,%10,%11,%12,%13,%14,%15," \
        "%16,%17,%18,%19,%20,%21,%22,%23,%24,%25,%26,%27,%28,%29,%30,%31}, [%32];" \
        : "=r"((r)[0]), "=r"((r)[1]), "=r"((r)[2]), "=r"((r)[3]), "=r"((r)[4]), "=r"((r)[5]), "=r"((r)[6]), "=r"((r)[7]), \
          "=r"((r)[8]), "=r"((r)[9]), "=r"((r)[10]), "=r"((r)[11]), "=r"((r)[12]), "=r"((r)[13]), "=r"((r)[14]), "=r"((r)[15]), \
          "=r"((r)[16]), "=r"((r)[17]), "=r"((r)[18]), "=r"((r)[19]), "=r"((r)[20]), "=r"((r)[21]), "=r"((r)[22]), "=r"((r)[23]), \
          "=r"((r)[24]), "=r"((r)[25]), "=r"((r)[26]), "=r"((r)[27]), "=r"((r)[28]), "=r"((r)[29]), "=r"((r)[30]), "=r"((r)[31]) \
        : "r"(ta))

// SW64 K-major descriptor: layout=4, version=1, SBO=32, LBO=1
static constexpr uint64_t DESC_SW64 =
    (uint64_t(4) << 61) | (uint64_t(1) << 46) | (uint64_t(32) << 32) | (uint64_t(1) << 16);
#define MK_DESC(a) (DESC_SW64 | ((uint64_t)((a) >> 4) & 0x3FFF))
// idesc kind::f16 cg2: F32 out, BF16 a/b, M=256 (16<<24), N=256 (32<<17)
#define IDESC_CG2 ((1u << 4) | (1u << 7) | (1u << 10) | (32u << 17) | (16u << 24))

__device__ __forceinline__ void mma_cg2(uint32_t d, uint64_t a, uint64_t b, uint32_t en) {
    asm volatile("{\n\t.reg .pred p;\n\tsetp.ne.u32 p, %4, 0;\n\t"
        "tcgen05.mma.cta_group::2.kind::f16 [%0], %1, %2, %3, {%5,%5,%5,%5,%5,%5,%5,%5}, p;\n\t}"
        :: "r"(d), "l"(a), "l"(b), "r"(IDESC_CG2), "r"(en), "r"(0u) : "memory");
}
#endif  // TC_OK

__device__ __forceinline__ uint32_t pack_hi(float a, float b, uint32_t& lo) {
    __nv_bfloat16 h0 = __float2bfloat16(a), h1 = __float2bfloat16(b);
    __nv_bfloat16 l0 = __float2bfloat16(a - __bfloat162float(h0));
    __nv_bfloat16 l1 = __float2bfloat16(b - __bfloat162float(h1));
    lo = (uint32_t)__bfloat16_as_ushort(l0) | ((uint32_t)__bfloat16_as_ushort(l1) << 16);
    return (uint32_t)__bfloat16_as_ushort(h0) | ((uint32_t)__bfloat16_as_ushort(h1) << 16);
}

// ---------------- routing ----------------
__global__ void k_zero() { if (threadIdx.x < E) g_counts[threadIdx.x] = 0; }

__global__ void k_router(const float* __restrict__ x, const float* __restrict__ gate,
                         float* __restrict__ logits_out, int T) {
    __shared__ float sg[E * H];
    for (int i = threadIdx.x; i < E * H; i += blockDim.x) sg[i] = gate[i];
    __syncthreads();
    int warp = threadIdx.x >> 5, lane = threadIdx.x & 31;
    int t = blockIdx.x * 8 + warp;
    if (t >= T) return;
    const float* xr = x + (size_t)t * H;
    float acc[E];
#pragma unroll
    for (int e = 0; e < E; e++) acc[e] = 0.f;
    for (int k = lane; k < H; k += 32) {
        float xv = xr[k];
#pragma unroll
        for (int e = 0; e < E; e++) acc[e] += xv * sg[e * H + k];
    }
#pragma unroll
    for (int e = 0; e < E; e++)
#pragma unroll
        for (int o = 16; o > 0; o >>= 1) acc[e] += __shfl_down_sync(0xffffffffu, acc[e], o);
    if (lane == 0) {
#pragma unroll
        for (int e = 0; e < E; e++) logits_out[(size_t)t * E + e] = acc[e];
        int e0 = 0; float l0 = acc[0];
#pragma unroll
        for (int e = 1; e < E; e++) if (acc[e] > l0) { l0 = acc[e]; e0 = e; }
        int e1 = -1; float l1 = -1e30f;
#pragma unroll
        for (int e = 0; e < E; e++) if (e != e0 && acc[e] > l1) { l1 = acc[e]; e1 = e; }
        float s = 0.f, pe[E];
#pragma unroll
        for (int e = 0; e < E; e++) { pe[e] = expf(acc[e] - l0); s += pe[e]; }
        float p0 = pe[e0] / s, p1 = pe[e1] / s;
        float inv = 1.f / (p0 + p1);
        int q0 = atomicAdd(&g_counts[e0], 1);
        g_list[e0 * T_MAX + q0] = (t << 1);
        g_wts[(t << 1)] = p0 * inv;
        int q1 = atomicAdd(&g_counts[e1], 1);
        g_list[e1 * T_MAX + q1] = (t << 1) | 1;
        g_wts[(t << 1) | 1] = p1 * inv;
    }
}

__global__ void k_base() {
    if (threadIdx.x == 0) {
        int s = 0, ps = 0;
#pragma unroll
        for (int e = 0; e < E; e++) {
            g_base[e] = s;  g_pbase[e] = ps;
            s += g_counts[e];
            ps += (g_counts[e] + 511) & ~511;
        }
    }
}

// fp32 -> bf16 hi/lo, pre-tiled + pre-swizzled
__global__ void k_split8(const float* __restrict__ src, __nv_bfloat16* __restrict__ hi,
                         __nv_bfloat16* __restrict__ lo, long n8, int K, int nkc) {
    long i = (long)blockIdx.x * blockDim.x + threadIdx.x;
    if (i >= n8) return;
    long f = i * 8;
    int row = (int)(f / K), k0 = (int)(f % K);
    int kc = k0 >> 5, c = (k0 & 31) >> 3;
    int rr = row & 127, tr = row >> 7;
    size_t off = ((size_t)tr * nkc + kc) * TB + (size_t)rr * 64 + ((c ^ ((rr >> 1) & 3)) << 4);
    const float4* s4 = (const float4*)(src + f);
    float4 a = s4[0], b = s4[1];
    float v[8] = {a.x, a.y, a.z, a.w, b.x, b.y, b.z, b.w};
    uint32_t ph[4], pl[4];
#pragma unroll
    for (int j = 0; j < 4; j++) ph[j] = pack_hi(v[2 * j], v[2 * j + 1], pl[j]);
    *(uint4*)((char*)hi + off) = make_uint4(ph[0], ph[1], ph[2], ph[3]);
    *(uint4*)((char*)lo + off) = make_uint4(pl[0], pl[1], pl[2], pl[3]);
}

// gather x rows into expert-grouped (padded) tiled hi/lo
__global__ void k_gather(const float* __restrict__ x, int total) {
    int g = blockIdx.x;
    if (g >= total) return;
    int e = 0;
#pragma unroll
    for (int k = 1; k < E; k++) if (g >= g_base[k]) e = k;
    int pos = g - g_base[e];
    int tok = g_list[e * T_MAX + pos] >> 1;
    int prow = g_pbase[e] + pos;
    int rr = prow & 127, tr = prow >> 7;
    int tid = threadIdx.x;                 // 0..127
    int kc = tid >> 2, c = tid & 3;
    size_t off = ((size_t)tr * NKC_H + kc) * TB + (size_t)rr * 64 + ((c ^ ((rr >> 1) & 3)) << 4);
    const float4* src = (const float4*)(x + (size_t)tok * H + tid * 8);
    float4 a = src[0], b = src[1];
    float v[8] = {a.x, a.y, a.z, a.w, b.x, b.y, b.z, b.w};
    uint32_t ph[4], pl[4];
#pragma unroll
    for (int j = 0; j < 4; j++) ph[j] = pack_hi(v[2 * j], v[2 * j + 1], pl[j]);
    *(uint4*)((char*)g_ax_hi + off) = make_uint4(ph[0], ph[1], ph[2], ph[3]);
    *(uint4*)((char*)g_ax_lo + off) = make_uint4(pl[0], pl[1], pl[2], pl[3]);
}

#define SM_T 1024

#if TC_OK
// one stage fill (6 tiles, 48KB) -> local full barrier
__device__ __forceinline__ void bulk6(uint32_t sb, int buf,
    const __nv_bfloat16* Ah, const __nv_bfloat16* Al, int trA, int nkcA,
    const __nv_bfloat16* Wh, const __nv_bfloat16* Wl, int trW, int nkcW, int kc) {
    uint32_t mb = sb + 8 + buf * 8;
    uint32_t dst = sb + SM_T + buf * 6 * TB;
    size_t a0 = ((size_t)trA * nkcA + kc) * TB;
    size_t a1 = ((size_t)(trA + 1) * nkcA + kc) * TB;
    size_t w  = ((size_t)trW * nkcW + kc) * TB;
    BULK(dst + 0 * TB, (const char*)Ah + a0, mb);
    BULK(dst + 1 * TB, (const char*)Al + a0, mb);
    BULK(dst + 2 * TB, (const char*)Ah + a1, mb);
    BULK(dst + 3 * TB, (const char*)Al + a1, mb);
    BULK(dst + 4 * TB, (const char*)Wh + w, mb);
    BULK(dst + 5 * TB, (const char*)Wl + w, mb);
}

// tid0-only cg2 pipeline: leader (rank0) MMAs + multicast commits; follower arrives remotely
__device__ void run_pipeline(uint32_t sb, uint32_t tm, int NCH, int rank,
    const __nv_bfloat16* Ah, const __nv_bfloat16* Al, int trA, int nkcA,
    const __nv_bfloat16* Wh, const __nv_bfloat16* Wl, int trW, int nkcW) {
    bulk6(sb, 0, Ah, Al, trA, nkcA, Wh, Wl, trW, nkcW, 0);
    bulk6(sb, 1, Ah, Al, trA, nkcA, Wh, Wl, trW, nkcW, 1);
    for (int i = 0; i < NCH; i++) {
        int b = i % 3;
        MBAR_WAIT(sb + 8 + b * 8, (i / 3) & 1);
        MBAR_EXPECT(sb + 8 + b * 8, 6 * TB);          // re-arm next phase
        if (rank == 0) {
            uint32_t tb = sb + SM_T + b * 6 * TB;
            uint64_t dA0h = MK_DESC(tb),          dA0l = MK_DESC(tb + TB);
            uint64_t dA1h = MK_DESC(tb + 2 * TB), dA1l = MK_DESC(tb + 3 * TB);
            uint64_t dWh  = MK_DESC(tb + 4 * TB), dWl  = MK_DESC(tb + 5 * TB);
#pragma unroll
            for (int ks = 0; ks < 2; ks++) {
                uint64_t o = (uint64_t)(2 * ks);
                uint32_t en = (i > 0 || ks > 0) ? 1u : 0u;
                mma_cg2(tm,       dA0h + o, dWh + o, en);
                mma_cg2(tm,       dA0h + o, dWl + o, 1);
                mma_cg2(tm,       dA0l + o, dWh + o, 1);
                mma_cg2(tm + 256, dA1h + o, dWh + o, en);
                mma_cg2(tm + 256, dA1h + o, dWl + o, 1);
                mma_cg2(tm + 256, dA1l + o, dWh + o, 1);
            }
            TC_COMMIT_MC2(sb + 32 + b * 8, 0x3);
        } else {
            ARRIVE_REMOTE0(sb + 8 + b * 8);
        }
        if (i + 2 < NCH) {
            int nb = (i + 2) % 3;
            if (i >= 1) MBAR_WAIT(sb + 32 + nb * 8, ((i - 1) / 3) & 1);
            bulk6(sb, nb, Ah, Al, trA, nkcA, Wh, Wl, trW, nkcW, i + 2);
        }
    }
    for (int c = NCH - 3; c < NCH; c++)
        MBAR_WAIT(sb + 32 + (c % 3) * 8, (c / 3) & 1);
}
#endif

// ---------------- cg2 GEMM13: pair BM=512, BN=128 ([D1|D3]=256 cols) ----------------
// cluster (2,1,1): pair id = blockIdx.x>>1, rank = ctarank
__global__ __launch_bounds__(256, 1) __cluster_dims__(2, 1, 1) void k_mma13() {
#if TC_OK
    int e = blockIdx.z;
    int cnt = g_counts[e];
    int row0 = (blockIdx.x >> 1) * 512;
    if (row0 >= cnt) return;
    int rank = (int)cta_rank();
    int n0 = blockIdx.y * 128;
    int rbase = g_pbase[e] + row0 + rank * 256;
    int trA = rbase >> 7;
    int trW = (e * FF + n0) >> 7;
    const __nv_bfloat16* Wh = rank ? g_w3h : g_w1h;
    const __nv_bfloat16* Wl = rank ? g_w3l : g_w1l;

    extern __shared__ char sm[];
    uint32_t sb = smem_u32(sm);
    int tid = threadIdx.x, wid = tid >> 5, lid = tid & 31;

    if (wid == 0) TC_ALLOC_CG2(sb, 512);
    if (tid == 0) {
#pragma unroll
        for (int b = 0; b < 3; b++) {
            MBAR_INIT(sb + 8 + b * 8, rank == 0 ? 2 : 1);   // full: leader expect + follower arrive
            MBAR_INIT(sb + 32 + b * 8, 1);                   // mmadone (multicast commit)
            MBAR_EXPECT(sb + 8 + b * 8, 6 * TB);
        }
    }
    __syncthreads();
    CLUSTER_SYNC();
    uint32_t tm;
    asm volatile("ld.shared.b32 %0, [%1];" : "=r"(tm) : "r"(sb));

    if (tid == 0)
        run_pipeline(sb, tm, NKC_H, rank, g_ax_hi, g_ax_lo, trA, NKC_H, Wh, Wl, trW, NKC_H);
    __syncthreads();
    TC_FENCE_AFTER();

    // epilogue: 8 warps = 2 accumulators x 4 subpartitions; local rows = a*128+sub*32+lid
    int a = wid >> 2, sub = wid & 3;
    int lrow = a * 128 + sub * 32 + lid;
    bool valid = (row0 + rank * 256 + lrow) < cnt;
    int prow = rbase + lrow;
    int rr = prow & 127, tr = prow >> 7, sw = (rr >> 1) & 3;
#pragma unroll
    for (int c0 = 0; c0 < 128; c0 += 32) {
        uint32_t d1[32], d3[32];
        TC_LD_X32(d1, tm + a * 256 + c0);
        TC_LD_X32(d3, tm + a * 256 + 128 + c0);
        TC_WAIT_LD();
        if (valid) {
            uint32_t ph[16], pl[16];
#pragma unroll
            for (int j = 0; j < 16; j++) {
                float h0 = __uint_as_float(d1[2 * j]),     v0 = __uint_as_float(d3[2 * j]);
                float h1 = __uint_as_float(d1[2 * j + 1]), v1 = __uint_as_float(d3[2 * j + 1]);
                float a0 = (h0 / (1.f + __expf(-h0))) * v0;
                float a1 = (h1 / (1.f + __expf(-h1))) * v1;
                ph[j] = pack_hi(a0, a1, pl[j]);
            }
            int kc = (n0 >> 5) + (c0 >> 5);
            size_t tbo = ((size_t)tr * NKC_F + kc) * TB + (size_t)rr * 64;
#pragma unroll
            for (int q = 0; q < 4; q++) {
                size_t o = tbo + ((q ^ sw) << 4);
                *(uint4*)((char*)g_act_hi + o) = make_uint4(ph[4 * q], ph[4 * q + 1], ph[4 * q + 2], ph[4 * q + 3]);
                *(uint4*)((char*)g_act_lo + o) = make_uint4(pl[4 * q], pl[4 * q + 1], pl[4 * q + 2], pl[4 * q + 3]);
            }
        }
    }
    TC_FENCE_BEFORE();
    __syncthreads();
    if (wid == 0) { TC_RELINQ_CG2(); TC_DEALLOC_CG2(tm, 512); }
    CLUSTER_SYNC();
#endif
}

// ---------------- cg2 GEMM2: pair BM=512, BN=256 ----------------
__global__ __launch_bounds__(256, 1) __cluster_dims__(2, 1, 1) void k_mma2() {
#if TC_OK
    int e = blockIdx.z;
    int cnt = g_counts[e];
    int row0 = (blockIdx.x >> 1) * 512;
    if (row0 >= cnt) return;
    int rank = (int)cta_rank();
    int n0 = blockIdx.y * 256;
    int rbase = g_pbase[e] + row0 + rank * 256;
    int trA = rbase >> 7;
    int trW = (e * H + n0 + rank * 128) >> 7;   // each CTA loads its half of B rows

    extern __shared__ char sm[];
    uint32_t sb = smem_u32(sm);
    int tid = threadIdx.x, wid = tid >> 5, lid = tid & 31;

    if (wid == 0) TC_ALLOC_CG2(sb, 512);
    if (tid == 0) {
#pragma unroll
        for (int b = 0; b < 3; b++) {
            MBAR_INIT(sb + 8 + b * 8, rank == 0 ? 2 : 1);
            MBAR_INIT(sb + 32 + b * 8, 1);
            MBAR_EXPECT(sb + 8 + b * 8, 6 * TB);
        }
    }
    __syncthreads();
    CLUSTER_SYNC();
    uint32_t tm;
    asm volatile("ld.shared.b32 %0, [%1];" : "=r"(tm) : "r"(sb));

    if (tid == 0)
        run_pipeline(sb, tm, NKC_F, rank, g_act_hi, g_act_lo, trA, NKC_F, g_w2h, g_w2l, trW, NKC_F);
    __syncthreads();
    TC_FENCE_AFTER();

    int a = wid >> 2, sub = wid & 3;
    int lrow = a * 128 + sub * 32 + lid;
    bool valid = (row0 + rank * 256 + lrow) < cnt;
    int ts = 0; float w = 0.f;
    if (valid) { ts = g_list[e * T_MAX + row0 + rank * 256 + lrow]; w = g_wts[ts]; }
    float* yrow = g_ybuf + (size_t)ts * H + n0;
#pragma unroll
    for (int c0 = 0; c0 < 256; c0 += 32) {
        uint32_t d[32];
        TC_LD_X32(d, tm + a * 256 + c0);
        TC_WAIT_LD();
        if (valid) {
            float4* dst = (float4*)(yrow + c0);
#pragma unroll
            for (int q = 0; q < 8; q++)
                dst[q] = make_float4(w * __uint_as_float(d[4 * q]), w * __uint_as_float(d[4 * q + 1]),
                                     w * __uint_as_float(d[4 * q + 2]), w * __uint_as_float(d[4 * q + 3]));
        }
    }
    TC_FENCE_BEFORE();
    __syncthreads();
    if (wid == 0) { TC_RELINQ_CG2(); TC_DEALLOC_CG2(tm, 512); }
    CLUSTER_SYNC();
#endif
}

__global__ void k_combine(float* __restrict__ out, int T) {
    int i = blockIdx.x * blockDim.x + threadIdx.x;
    int total = T * (H / 4);
    if (i >= total) return;
    int t = i / (H / 4);
    int h4 = i - t * (H / 4);
    const float4* yb = (const float4*)g_ybuf;
    float4 a = yb[(size_t)(2 * t) * (H / 4) + h4];
    float4 b = yb[(size_t)(2 * t + 1) * (H / 4) + h4];
    ((float4*)out)[i] = make_float4(a.x + b.x, a.y + b.y, a.z + b.z, a.w + b.w);
}

// ---------------- launch ----------------
extern "C" void kernel_launch(void* const* d_in, const int* in_sizes, int n_in,
                              void* d_out, int out_size) {
    const float* x;
    const float* gate;
    if (in_sizes[0] > in_sizes[1]) { x = (const float*)d_in[0]; gate = (const float*)d_in[1]; }
    else                           { gate = (const float*)d_in[0]; x = (const float*)d_in[1]; }
    const float* w1 = (const float*)d_in[2];
    const float* w2 = (const float*)d_in[3];
    const float* w3 = (const float*)d_in[4];
    int T = (in_sizes[0] > in_sizes[1] ? in_sizes[0] : in_sizes[1]) / H;

    float* out = (float*)d_out;
    float* logits_out = out + (size_t)T * H;

    int smem = SM_T + 3 * 6 * TB;  // 148,480
    cudaFuncSetAttribute(k_mma13, cudaFuncAttributeMaxDynamicSharedMemorySize, smem);
    cudaFuncSetAttribute(k_mma2,  cudaFuncAttributeMaxDynamicSharedMemorySize, smem);

    __nv_bfloat16 *w1h, *w1l, *w3h, *w3l, *w2h, *w2l;
    cudaGetSymbolAddress((void**)&w1h, g_w1h); cudaGetSymbolAddress((void**)&w1l, g_w1l);
    cudaGetSymbolAddress((void**)&w3h, g_w3h); cudaGetSymbolAddress((void**)&w3l, g_w3l);
    cudaGetSymbolAddress((void**)&w2h, g_w2h); cudaGetSymbolAddress((void**)&w2l, g_w2l);

    k_zero<<<1, 32>>>();
    k_router<<<(T + 7) / 8, 256>>>(x, gate, logits_out, T);
    k_base<<<1, 1>>>();

    long n8 = (long)E * FF * H / 8;
    int sblk = (int)((n8 + 255) / 256);
    k_split8<<<sblk, 256>>>(w1, w1h, w1l, n8, H, NKC_H);
    k_split8<<<sblk, 256>>>(w3, w3h, w3l, n8, H, NKC_H);
    k_split8<<<sblk, 256>>>(w2, w2h, w2l, n8, FF, NKC_F);
    k_gather<<<2 * T, 128>>>(x, 2 * T);

    // cg2 launches: cluster (2,1,1) via cudaLaunchKernelEx (example-faithful)
    cudaLaunchAttribute attrs[1];
    attrs[0].id = cudaLaunchAttributeClusterDimension;
    attrs[0].val.clusterDim.x = 2; attrs[0].val.clusterDim.y = 1; attrs[0].val.clusterDim.z = 1;

    cudaLaunchConfig_t cfg13 = {};
    cfg13.gridDim  = dim3(32, FF / 128, E);   // x: 16 pairs (worst-case cnt=8192), early exit
    cfg13.blockDim = dim3(256, 1, 1);
    cfg13.dynamicSmemBytes = smem;
    cfg13.attrs = attrs; cfg13.numAttrs = 1;
    cudaLaunchKernelEx(&cfg13, k_mma13);

    cudaLaunchConfig_t cfg2 = {};
    cfg2.gridDim  = dim3(32, H / 256, E);
    cfg2.blockDim = dim3(256, 1, 1);
    cfg2.dynamicSmemBytes = smem;
    cfg2.attrs = attrs; cfg2.numAttrs = 1;
    cudaLaunchKernelEx(&cfg2, k_mma2);

    k_combine<<<(T * (H / 4) + 255) / 256, 256>>>(out, T);
}